// round 11
// baseline (speedup 1.0000x reference)
#include <cuda_runtime.h>
#include <cuda_bf16.h>
#include <math.h>
#include <stdint.h>

// Problem constants
#define TSEQ    2048
#define BATCH   2
#define DMODEL  1024
#define NHEAD   16
#define HEADDIM 64
#define FFDIM   4096
#define NLAYER  4
#define ROWS    (BATCH * TSEQ)          // 4096
#define QKVDIM  (3 * DMODEL)            // 3072
#define QKPITCH (2 * DMODEL)            // 2048 (Q cols 0..1023, K cols 1024..2047)

// -------------------- scratch (allocation-free) --------------------
__device__ float g_x  [ROWS * DMODEL];          // residual stream (fp32)
__device__ __nv_bfloat16 g_xn_h [ROWS * DMODEL];
__device__ __nv_bfloat16 g_xn_l [ROWS * DMODEL];
__device__ __nv_bfloat16 g_att_h[ROWS * DMODEL];
__device__ __nv_bfloat16 g_att_l[ROWS * DMODEL];
__device__ __nv_bfloat16 g_h_h  [ROWS * FFDIM];
__device__ __nv_bfloat16 g_h_l  [ROWS * FFDIM];
__device__ __nv_bfloat16 g_qk_h [ROWS * QKPITCH];
__device__ __nv_bfloat16 g_qk_l [ROWS * QKPITCH];
__device__ __nv_bfloat16 g_vt_h [BATCH * NHEAD * HEADDIM * TSEQ];
__device__ __nv_bfloat16 g_vt_l [BATCH * NHEAD * HEADDIM * TSEQ];
__device__ __nv_bfloat16 g_wi_h[NLAYER * QKVDIM * DMODEL];
__device__ __nv_bfloat16 g_wi_l[NLAYER * QKVDIM * DMODEL];
__device__ __nv_bfloat16 g_wo_h[NLAYER * DMODEL * DMODEL];
__device__ __nv_bfloat16 g_wo_l[NLAYER * DMODEL * DMODEL];
__device__ __nv_bfloat16 g_w1_h[NLAYER * FFDIM * DMODEL];
__device__ __nv_bfloat16 g_w1_l[NLAYER * FFDIM * DMODEL];
__device__ __nv_bfloat16 g_w2_h[NLAYER * DMODEL * FFDIM];
__device__ __nv_bfloat16 g_w2_l[NLAYER * DMODEL * FFDIM];

// -------------------- helpers --------------------
__device__ __forceinline__ void cp_async16(uint32_t smem, const void* g) {
    asm volatile("cp.async.cg.shared.global [%0], [%1], 16;\n" :: "r"(smem), "l"(g));
}
__device__ __forceinline__ void cp_commit() {
    asm volatile("cp.async.commit_group;\n" ::: "memory");
}
__device__ __forceinline__ void cp_wait0() {
    asm volatile("cp.async.wait_group 0;\n" ::: "memory");
}
__device__ __forceinline__ uint32_t smem_u32(const void* p) {
    return (uint32_t)__cvta_generic_to_shared(p);
}
__device__ __forceinline__ void split2(float v, __nv_bfloat16& h, __nv_bfloat16& l) {
    h = __float2bfloat16(v);
    l = __float2bfloat16(v - __bfloat162float(h));
}
__device__ __forceinline__ void splitpack(float a, float b, uint32_t& hi, uint32_t& lo) {
    __nv_bfloat16 ha, la, hb, lb;
    split2(a, ha, la); split2(b, hb, lb);
    __nv_bfloat162 ph; ph.x = ha; ph.y = hb;
    __nv_bfloat162 pl; pl.x = la; pl.y = lb;
    hi = *(uint32_t*)&ph; lo = *(uint32_t*)&pl;
}
__device__ __forceinline__ void mma_bf16(float* d, const uint32_t* a, uint32_t b0, uint32_t b1) {
    asm volatile(
        "mma.sync.aligned.m16n8k16.row.col.f32.bf16.bf16.f32 "
        "{%0,%1,%2,%3}, {%4,%5,%6,%7}, {%8,%9}, {%0,%1,%2,%3};\n"
        : "+f"(d[0]), "+f"(d[1]), "+f"(d[2]), "+f"(d[3])
        : "r"(a[0]), "r"(a[1]), "r"(a[2]), "r"(a[3]),
          "r"(b0), "r"(b1));
}
__device__ __forceinline__ void ldsm4(uint32_t* r, uint32_t addr) {
    asm volatile("ldmatrix.sync.aligned.m8n8.x4.shared.b16 {%0,%1,%2,%3}, [%4];"
        : "=r"(r[0]), "=r"(r[1]), "=r"(r[2]), "=r"(r[3]) : "r"(addr));
}

// -------------------- copy --------------------
__global__ void copy_kernel(const float4* __restrict__ in, float4* __restrict__ out, int n4) {
    int i = blockIdx.x * blockDim.x + threadIdx.x;
    if (i < n4) out[i] = in[i];
}

// -------------------- weight split --------------------
__global__ void split_kernel(const float4* __restrict__ in,
                             __nv_bfloat162* __restrict__ hi,
                             __nv_bfloat162* __restrict__ lo, int n4) {
    int i = blockIdx.x * blockDim.x + threadIdx.x;
    if (i >= n4) return;
    float4 v = in[i];
    uint32_t h0, l0, h1, l1;
    splitpack(v.x, v.y, h0, l0);
    splitpack(v.z, v.w, h1, l1);
    hi[i * 2 + 0] = *(__nv_bfloat162*)&h0; hi[i * 2 + 1] = *(__nv_bfloat162*)&h1;
    lo[i * 2 + 0] = *(__nv_bfloat162*)&l0; lo[i * 2 + 1] = *(__nv_bfloat162*)&l1;
}

// -------------------- layernorm (fp32 out — final) --------------------
__global__ void __launch_bounds__(256) ln_kernel(
    const float* __restrict__ in, const float* __restrict__ w,
    const float* __restrict__ b, float* __restrict__ out)
{
    int row = blockIdx.x;
    int tid = threadIdx.x;
    const float4* ip = (const float4*)(in + (size_t)row * DMODEL);
    float4 v = ip[tid];
    float s  = v.x + v.y + v.z + v.w;
    float sq = v.x * v.x + v.y * v.y + v.z * v.z + v.w * v.w;
    #pragma unroll
    for (int o = 16; o > 0; o >>= 1) {
        s  += __shfl_xor_sync(0xffffffffu, s,  o);
        sq += __shfl_xor_sync(0xffffffffu, sq, o);
    }
    __shared__ float reds[8], redq[8];
    int lane = tid & 31, wid = tid >> 5;
    if (lane == 0) { reds[wid] = s; redq[wid] = sq; }
    __syncthreads();
    float ts = 0.f, tq = 0.f;
    #pragma unroll
    for (int i = 0; i < 8; i++) { ts += reds[i]; tq += redq[i]; }
    float mean = ts * (1.0f / DMODEL);
    float var  = tq * (1.0f / DMODEL) - mean * mean;
    float rstd = rsqrtf(var + 1e-5f);
    float4 wv = ((const float4*)w)[tid];
    float4 bv = ((const float4*)b)[tid];
    float4 r;
    r.x = (v.x - mean) * rstd * wv.x + bv.x;
    r.y = (v.y - mean) * rstd * wv.y + bv.y;
    r.z = (v.z - mean) * rstd * wv.z + bv.z;
    r.w = (v.w - mean) * rstd * wv.w + bv.w;
    ((float4*)(out + (size_t)row * DMODEL))[tid] = r;
}

// -------------------- layernorm (dual-bf16 out) --------------------
__global__ void __launch_bounds__(256) ln_dual_kernel(
    const float* __restrict__ in, const float* __restrict__ w,
    const float* __restrict__ b,
    __nv_bfloat16* __restrict__ oh, __nv_bfloat16* __restrict__ ol)
{
    int row = blockIdx.x;
    int tid = threadIdx.x;
    const float4* ip = (const float4*)(in + (size_t)row * DMODEL);
    float4 v = ip[tid];
    float s  = v.x + v.y + v.z + v.w;
    float sq = v.x * v.x + v.y * v.y + v.z * v.z + v.w * v.w;
    #pragma unroll
    for (int o = 16; o > 0; o >>= 1) {
        s  += __shfl_xor_sync(0xffffffffu, s,  o);
        sq += __shfl_xor_sync(0xffffffffu, sq, o);
    }
    __shared__ float reds[8], redq[8];
    int lane = tid & 31, wid = tid >> 5;
    if (lane == 0) { reds[wid] = s; redq[wid] = sq; }
    __syncthreads();
    float ts = 0.f, tq = 0.f;
    #pragma unroll
    for (int i = 0; i < 8; i++) { ts += reds[i]; tq += redq[i]; }
    float mean = ts * (1.0f / DMODEL);
    float var  = tq * (1.0f / DMODEL) - mean * mean;
    float rstd = rsqrtf(var + 1e-5f);
    float4 wv = ((const float4*)w)[tid];
    float4 bv = ((const float4*)b)[tid];
    float r0 = (v.x - mean) * rstd * wv.x + bv.x;
    float r1 = (v.y - mean) * rstd * wv.y + bv.y;
    float r2 = (v.z - mean) * rstd * wv.z + bv.z;
    float r3 = (v.w - mean) * rstd * wv.w + bv.w;
    uint32_t ph0, pl0, ph1, pl1;
    splitpack(r0, r1, ph0, pl0);
    splitpack(r2, r3, ph1, pl1);
    size_t base = (size_t)row * DMODEL + tid * 4;
    *(uint32_t*)(oh + base)     = ph0;
    *(uint32_t*)(oh + base + 2) = ph1;
    *(uint32_t*)(ol + base)     = pl0;
    *(uint32_t*)(ol + base + 2) = pl1;
}

// -------------------- bf16 split-3 tensor-core GEMM (mma + ldmatrix) --------------------
// Block 128x128, BK=32, 8 warps (4M x 2N), warp tile 32x64.
// EPI: 1 = bias+GELU -> dual-bf16 ; 2 = bias+residual -> fp32 ;
//      3 = bias -> QK dual planes + V transposed dual planes
#define GPITCH 40
#define A_ELE (128 * GPITCH)
#define W_ELE (128 * GPITCH)
#define STG_ELE (2 * A_ELE + 2 * W_ELE)
#define GEMM_SMEM (2 * STG_ELE * 2)           // 81920 bytes

template <int EPI>
__global__ void __launch_bounds__(256, 2) gemm_bf16(
    const __nv_bfloat16* __restrict__ Ah, const __nv_bfloat16* __restrict__ Al,
    const __nv_bfloat16* __restrict__ Wh, const __nv_bfloat16* __restrict__ Wl,
    const float* __restrict__ bias, const float* __restrict__ res,
    float* __restrict__ Cf, __nv_bfloat16* __restrict__ Ch, __nv_bfloat16* __restrict__ Cl,
    __nv_bfloat16* __restrict__ Vth, __nv_bfloat16* __restrict__ Vtl,
    int M, int N, int K)
{
    extern __shared__ __nv_bfloat16 smem[];
    uint32_t sbase = smem_u32(smem);

    int tid  = threadIdx.x;
    int lane = tid & 31;
    int wid  = tid >> 5;
    int warpM = (wid >> 1) * 32;
    int warpN = (wid & 1) * 64;
    int m0 = blockIdx.y * 128;
    int n0 = blockIdx.x * 128;

    int gr = lane >> 2;
    int gc = lane & 3;
    int lane15 = lane & 15;
    int halfB  = (lane >> 4) * 16;

    // ldmatrix per-lane offsets (within a plane)
    uint32_t aoff[2], boff[4];
    #pragma unroll
    for (int mt = 0; mt < 2; mt++)
        aoff[mt] = (uint32_t)((warpM + mt * 16 + lane15) * 80 + halfB);
    #pragma unroll
    for (int np = 0; np < 4; np++)
        boff[np] = (uint32_t)((warpN + np * 16 + lane15) * 80 + halfB);

    float acc[2][8][4];
    #pragma unroll
    for (int i = 0; i < 2; i++)
        #pragma unroll
        for (int j = 0; j < 8; j++)
            #pragma unroll
            for (int c = 0; c < 4; c++) acc[i][j][c] = 0.f;

    int KT = K >> 5;

    auto load_chunk = [&](int kt) {
        uint32_t sb = sbase + (uint32_t)(kt & 1) * STG_ELE * 2;
        int k0 = kt << 5;
        #pragma unroll
        for (int i = 0; i < 2; i++) {
            int idx = tid + i * 256;
            int row = idx >> 2;
            int k16 = idx & 3;
            uint32_t so = (uint32_t)(row * 80 + k16 * 16);
            size_t ga = (size_t)(m0 + row) * K + k0 + k16 * 8;
            size_t gw = (size_t)(n0 + row) * K + k0 + k16 * 8;
            cp_async16(sb + so, Ah + ga);
            cp_async16(sb + A_ELE * 2 + so, Al + ga);
            cp_async16(sb + 2 * A_ELE * 2 + so, Wh + gw);
            cp_async16(sb + (2 * A_ELE + W_ELE) * 2 + so, Wl + gw);
        }
        cp_commit();
    };

    load_chunk(0);

    for (int kt = 0; kt < KT; kt++) {
        cp_wait0();
        __syncthreads();
        if (kt + 1 < KT) load_chunk(kt + 1);

        uint32_t stg = sbase + (uint32_t)(kt & 1) * STG_ELE * 2;
        uint32_t pAh = stg;
        uint32_t pAl = stg + A_ELE * 2;
        uint32_t pWh = stg + 2 * A_ELE * 2;
        uint32_t pWl = stg + (2 * A_ELE + W_ELE) * 2;

        #pragma unroll
        for (int ks = 0; ks < 2; ks++) {
            uint32_t ko = (uint32_t)(ks * 32);
            uint32_t ah[2][4], al[2][4];
            ldsm4(ah[0], pAh + aoff[0] + ko);
            ldsm4(ah[1], pAh + aoff[1] + ko);
            ldsm4(al[0], pAl + aoff[0] + ko);
            ldsm4(al[1], pAl + aoff[1] + ko);
            #pragma unroll
            for (int np = 0; np < 4; np++) {
                uint32_t bh[4], bl[4];
                ldsm4(bh, pWh + boff[np] + ko);
                ldsm4(bl, pWl + boff[np] + ko);
                #pragma unroll
                for (int mt = 0; mt < 2; mt++) {
                    // nt = 2np : frag {bh[0], bh[2]}
                    mma_bf16(acc[mt][2 * np],     ah[mt], bh[0], bh[2]);
                    mma_bf16(acc[mt][2 * np],     ah[mt], bl[0], bl[2]);
                    mma_bf16(acc[mt][2 * np],     al[mt], bh[0], bh[2]);
                    // nt = 2np+1 : frag {bh[1], bh[3]}
                    mma_bf16(acc[mt][2 * np + 1], ah[mt], bh[1], bh[3]);
                    mma_bf16(acc[mt][2 * np + 1], ah[mt], bl[1], bl[3]);
                    mma_bf16(acc[mt][2 * np + 1], al[mt], bh[1], bh[3]);
                }
            }
        }
        __syncthreads();
    }

    // ---- epilogue ----
    #pragma unroll
    for (int mt = 0; mt < 2; mt++) {
        int r0 = m0 + warpM + mt * 16 + gr;
        #pragma unroll
        for (int nt = 0; nt < 8; nt++) {
            int col = n0 + warpN + nt * 8 + 2 * gc;
            float b0 = bias[col], b1 = bias[col + 1];
            #pragma unroll
            for (int half = 0; half < 2; half++) {
                int row = r0 + half * 8;
                float v0 = acc[mt][nt][2 * half + 0] + b0;
                float v1 = acc[mt][nt][2 * half + 1] + b1;
                if (EPI == 1) {
                    v0 = 0.5f * v0 * (1.0f + erff(v0 * 0.70710678118654752f));
                    v1 = 0.5f * v1 * (1.0f + erff(v1 * 0.70710678118654752f));
                    uint32_t ph, pl;
                    splitpack(v0, v1, ph, pl);
                    size_t base = (size_t)row * N + col;
                    *(uint32_t*)(Ch + base) = ph;
                    *(uint32_t*)(Cl + base) = pl;
                } else if (EPI == 2) {
                    const float2 rv = *(const float2*)(res + (size_t)row * N + col);
                    v0 += rv.x; v1 += rv.y;
                    float2 o2; o2.x = v0; o2.y = v1;
                    *(float2*)(Cf + (size_t)row * N + col) = o2;
                } else {   // EPI == 3: QKV epilogue
                    if (col >= 2 * DMODEL) {
                        int c  = col - 2 * DMODEL;
                        int hh = c >> 6, d = c & 63;
                        int bb = row >> 11, t = row & (TSEQ - 1);
                        size_t vi = ((size_t)((bb * NHEAD + hh) * HEADDIM + d)) * TSEQ + t;
                        __nv_bfloat16 h0, l0v, h1, l1v;
                        split2(v0, h0, l0v); split2(v1, h1, l1v);
                        Vth[vi] = h0;        Vtl[vi] = l0v;
                        Vth[vi + TSEQ] = h1; Vtl[vi + TSEQ] = l1v;
                    } else {
                        uint32_t ph, pl;
                        splitpack(v0, v1, ph, pl);
                        size_t base = (size_t)row * QKPITCH + col;
                        *(uint32_t*)(Ch + base) = ph;
                        *(uint32_t*)(Cl + base) = pl;
                    }
                }
            }
        }
    }
}

// -------------------- mma flash attention (bf16 split-3, causal + ALiBi) --------------------
#define KV_PITCH_B 144
#define KV_TILE_B (64 * KV_PITCH_B)
#define ATT_STAGE (4 * KV_TILE_B)
#define ATT_SMEM  (2 * ATT_STAGE)              // 73728

__global__ void __launch_bounds__(128) attn_mma_kernel(
    const __nv_bfloat16* __restrict__ qkh, const __nv_bfloat16* __restrict__ qkl,
    const __nv_bfloat16* __restrict__ vth, const __nv_bfloat16* __restrict__ vtl,
    __nv_bfloat16* __restrict__ oh, __nv_bfloat16* __restrict__ ol)
{
    extern __shared__ char asmem[];
    uint32_t sbase = smem_u32(asmem);

    int b = blockIdx.z, h = blockIdx.y;
    int qt = gridDim.x - 1 - blockIdx.x;
    int tid = threadIdx.x, lane = tid & 31, w = tid >> 5;
    int gr = lane >> 2, gc = lane & 3;
    int lane15 = lane & 15;
    int halfB  = (lane >> 4) * 16;

    uint32_t noff[4];
    #pragma unroll
    for (int np = 0; np < 4; np++)
        noff[np] = (uint32_t)((np * 16 + lane15) * KV_PITCH_B + halfB);

    int hcol = h * HEADDIM;
    int qrow0 = b * TSEQ + qt * 64;

    uint32_t qh[4][4], ql[4][4];
    {
        const __nv_bfloat16* qp  = qkh + (size_t)(qrow0 + w * 16) * QKPITCH + hcol;
        const __nv_bfloat16* qpl = qkl + (size_t)(qrow0 + w * 16) * QKPITCH + hcol;
        #pragma unroll
        for (int kc = 0; kc < 4; kc++) {
            int c = kc * 16 + 2 * gc;
            qh[kc][0] = *(const uint32_t*)(qp  + (size_t)gr * QKPITCH + c);
            qh[kc][1] = *(const uint32_t*)(qp  + (size_t)(gr + 8) * QKPITCH + c);
            qh[kc][2] = *(const uint32_t*)(qp  + (size_t)gr * QKPITCH + c + 8);
            qh[kc][3] = *(const uint32_t*)(qp  + (size_t)(gr + 8) * QKPITCH + c + 8);
            ql[kc][0] = *(const uint32_t*)(qpl + (size_t)gr * QKPITCH + c);
            ql[kc][1] = *(const uint32_t*)(qpl + (size_t)(gr + 8) * QKPITCH + c);
            ql[kc][2] = *(const uint32_t*)(qpl + (size_t)gr * QKPITCH + c + 8);
            ql[kc][3] = *(const uint32_t*)(qpl + (size_t)(gr + 8) * QKPITCH + c + 8);
        }
    }

    auto load_kv = [&](int kt, int s) {
        uint32_t sb = sbase + (uint32_t)s * ATT_STAGE;
        const __nv_bfloat16* Kh = qkh + (size_t)(b * TSEQ + kt * 64) * QKPITCH + DMODEL + hcol;
        const __nv_bfloat16* Kl = qkl + (size_t)(b * TSEQ + kt * 64) * QKPITCH + DMODEL + hcol;
        size_t vbase = (size_t)((b * NHEAD + h) * HEADDIM) * TSEQ + kt * 64;
        #pragma unroll
        for (int i = 0; i < 4; i++) {
            int idx = tid + i * 128;
            int r   = idx >> 3;
            int c16 = idx & 7;
            uint32_t so = (uint32_t)(r * KV_PITCH_B + c16 * 16);
            cp_async16(sb + so,                  Kh  + (size_t)r * QKPITCH + c16 * 8);
            cp_async16(sb + KV_TILE_B + so,      Kl  + (size_t)r * QKPITCH + c16 * 8);
            cp_async16(sb + 2 * KV_TILE_B + so,  vth + vbase + (size_t)r * TSEQ + c16 * 8);
            cp_async16(sb + 3 * KV_TILE_B + so,  vtl + vbase + (size_t)r * TSEQ + c16 * 8);
        }
        cp_commit();
    };

    float m0 = -INFINITY, m1 = -INFINITY, l0 = 0.f, l1 = 0.f;
    float acc_o[8][4];
    #pragma unroll
    for (int nt = 0; nt < 8; nt++)
        #pragma unroll
        for (int j = 0; j < 4; j++) acc_o[nt][j] = 0.f;

    float slope = exp2f(-0.5f * (float)(h + 1));
    int qpos0 = qt * 64 + w * 16 + gr;

    load_kv(0, 0);

    for (int kt = 0; kt <= qt; kt++) {
        int s = kt & 1;
        cp_wait0();
        __syncthreads();
        if (kt < qt) load_kv(kt + 1, s ^ 1);

        uint32_t Ksh = sbase + (uint32_t)s * ATT_STAGE;
        uint32_t Ksl = Ksh + KV_TILE_B;
        uint32_t Vsh = Ksh + 2 * KV_TILE_B;
        uint32_t Vsl = Ksh + 3 * KV_TILE_B;

        // ---- S = Q K^T ----
        float sacc[8][4];
        #pragma unroll
        for (int nt = 0; nt < 8; nt++)
            #pragma unroll
            for (int j = 0; j < 4; j++) sacc[nt][j] = 0.f;

        #pragma unroll
        for (int kc = 0; kc < 4; kc++) {
            uint32_t ko = (uint32_t)(kc * 32);
            #pragma unroll
            for (int np = 0; np < 4; np++) {
                uint32_t bh[4], bl[4];
                ldsm4(bh, Ksh + noff[np] + ko);
                ldsm4(bl, Ksl + noff[np] + ko);
                mma_bf16(sacc[2 * np],     qh[kc], bh[0], bh[2]);
                mma_bf16(sacc[2 * np],     qh[kc], bl[0], bl[2]);
                mma_bf16(sacc[2 * np],     ql[kc], bh[0], bh[2]);
                mma_bf16(sacc[2 * np + 1], qh[kc], bh[1], bh[3]);
                mma_bf16(sacc[2 * np + 1], qh[kc], bl[1], bl[3]);
                mma_bf16(sacc[2 * np + 1], ql[kc], bh[1], bh[3]);
            }
        }

        // ---- mask + ALiBi + online softmax ----
        int kbase = kt * 64;
        float tmax0 = -INFINITY, tmax1 = -INFINITY;
        #pragma unroll
        for (int nt = 0; nt < 8; nt++) {
            #pragma unroll
            for (int j = 0; j < 4; j++) {
                int kp = kbase + nt * 8 + 2 * gc + (j & 1);
                int qp = qpos0 + ((j >> 1) << 3);
                float sv = (kp <= qp)
                    ? sacc[nt][j] * 0.125f + slope * (float)(kp - qp)
                    : -INFINITY;
                sacc[nt][j] = sv;
                if (j < 2) tmax0 = fmaxf(tmax0, sv);
                else       tmax1 = fmaxf(tmax1, sv);
            }
        }
        tmax0 = fmaxf(tmax0, __shfl_xor_sync(0xffffffffu, tmax0, 1));
        tmax0 = fmaxf(tmax0, __shfl_xor_sync(0xffffffffu, tmax0, 2));
        tmax1 = fmaxf(tmax1, __shfl_xor_sync(0xffffffffu, tmax1, 1));
        tmax1 = fmaxf(tmax1, __shfl_xor_sync(0xffffffffu, tmax1, 2));

        float nm0 = fmaxf(m0, tmax0);
        float nm1 = fmaxf(m1, tmax1);
        float corr0 = __expf(m0 - nm0);
        float corr1 = __expf(m1 - nm1);
        m0 = nm0; m1 = nm1;
        l0 *= corr0; l1 *= corr1;
        #pragma unroll
        for (int nt = 0; nt < 8; nt++) {
            acc_o[nt][0] *= corr0; acc_o[nt][1] *= corr0;
            acc_o[nt][2] *= corr1; acc_o[nt][3] *= corr1;
        }

        float ts0 = 0.f, ts1 = 0.f;
        #pragma unroll
        for (int nt = 0; nt < 8; nt++) {
            #pragma unroll
            for (int j = 0; j < 4; j++) {
                float p = __expf(sacc[nt][j] - ((j < 2) ? m0 : m1));
                sacc[nt][j] = p;
                if (j < 2) ts0 += p; else ts1 += p;
            }
        }
        ts0 += __shfl_xor_sync(0xffffffffu, ts0, 1);
        ts0 += __shfl_xor_sync(0xffffffffu, ts0, 2);
        ts1 += __shfl_xor_sync(0xffffffffu, ts1, 1);
        ts1 += __shfl_xor_sync(0xffffffffu, ts1, 2);
        l0 += ts0; l1 += ts1;

        // ---- O += P V ----
        #pragma unroll
        for (int kc = 0; kc < 4; kc++) {
            uint32_t ph[4], pl[4];
            splitpack(sacc[2 * kc][0],     sacc[2 * kc][1],     ph[0], pl[0]);
            splitpack(sacc[2 * kc][2],     sacc[2 * kc][3],     ph[1], pl[1]);
            splitpack(sacc[2 * kc + 1][0], sacc[2 * kc + 1][1], ph[2], pl[2]);
            splitpack(sacc[2 * kc + 1][2], sacc[2 * kc + 1][3], ph[3], pl[3]);
            uint32_t ko = (uint32_t)(kc * 32);
            #pragma unroll
            for (int np = 0; np < 4; np++) {
                uint32_t bh[4], bl[4];
                ldsm4(bh, Vsh + noff[np] + ko);
                ldsm4(bl, Vsl + noff[np] + ko);
                mma_bf16(acc_o[2 * np],     ph, bh[0], bh[2]);
                mma_bf16(acc_o[2 * np],     ph, bl[0], bl[2]);
                mma_bf16(acc_o[2 * np],     pl, bh[0], bh[2]);
                mma_bf16(acc_o[2 * np + 1], ph, bh[1], bh[3]);
                mma_bf16(acc_o[2 * np + 1], ph, bl[1], bl[3]);
                mma_bf16(acc_o[2 * np + 1], pl, bh[1], bh[3]);
            }
        }
    }

    // ---- epilogue ----
    float inv0 = 1.0f / l0, inv1 = 1.0f / l1;
    int r0 = qrow0 + w * 16 + gr;
    #pragma unroll
    for (int nt = 0; nt < 8; nt++) {
        int col = hcol + nt * 8 + 2 * gc;
        uint32_t ph0, pl0, ph1, pl1;
        splitpack(acc_o[nt][0] * inv0, acc_o[nt][1] * inv0, ph0, pl0);
        splitpack(acc_o[nt][2] * inv1, acc_o[nt][3] * inv1, ph1, pl1);
        size_t b0 = (size_t)r0 * DMODEL + col;
        size_t b1 = (size_t)(r0 + 8) * DMODEL + col;
        *(uint32_t*)(oh + b0) = ph0; *(uint32_t*)(ol + b0) = pl0;
        *(uint32_t*)(oh + b1) = ph1; *(uint32_t*)(ol + b1) = pl1;
    }
}

// -------------------- launch --------------------
extern "C" void kernel_launch(void* const* d_in, const int* in_sizes, int n_in,
                              void* d_out, int out_size)
{
    const float* x        = (const float*)d_in[0];
    const float* in_w     = (const float*)d_in[1];
    const float* in_b     = (const float*)d_in[2];
    const float* out_w    = (const float*)d_in[3];
    const float* out_b    = (const float*)d_in[4];
    const float* f1_w     = (const float*)d_in[5];
    const float* f1_b     = (const float*)d_in[6];
    const float* f2_w     = (const float*)d_in[7];
    const float* f2_b     = (const float*)d_in[8];
    const float* ln1_w    = (const float*)d_in[9];
    const float* ln1_b    = (const float*)d_in[10];
    const float* ln2_w    = (const float*)d_in[11];
    const float* ln2_b    = (const float*)d_in[12];
    const float* final_w  = (const float*)d_in[13];
    const float* final_b  = (const float*)d_in[14];

    float *x_;
    __nv_bfloat16 *xnh, *xnl, *atth, *attl, *hh, *hl;
    __nv_bfloat16 *qkh, *qkl, *vth, *vtl;
    __nv_bfloat16 *wih, *wil, *woh, *wol, *w1h, *w1l, *w2h, *w2l;
    cudaGetSymbolAddress((void**)&x_,   g_x);
    cudaGetSymbolAddress((void**)&xnh,  g_xn_h);
    cudaGetSymbolAddress((void**)&xnl,  g_xn_l);
    cudaGetSymbolAddress((void**)&atth, g_att_h);
    cudaGetSymbolAddress((void**)&attl, g_att_l);
    cudaGetSymbolAddress((void**)&hh,   g_h_h);
    cudaGetSymbolAddress((void**)&hl,   g_h_l);
    cudaGetSymbolAddress((void**)&qkh,  g_qk_h);
    cudaGetSymbolAddress((void**)&qkl,  g_qk_l);
    cudaGetSymbolAddress((void**)&vth,  g_vt_h);
    cudaGetSymbolAddress((void**)&vtl,  g_vt_l);
    cudaGetSymbolAddress((void**)&wih,  g_wi_h);
    cudaGetSymbolAddress((void**)&wil,  g_wi_l);
    cudaGetSymbolAddress((void**)&woh,  g_wo_h);
    cudaGetSymbolAddress((void**)&wol,  g_wo_l);
    cudaGetSymbolAddress((void**)&w1h,  g_w1_h);
    cudaGetSymbolAddress((void**)&w1l,  g_w1_l);
    cudaGetSymbolAddress((void**)&w2h,  g_w2_h);
    cudaGetSymbolAddress((void**)&w2l,  g_w2_l);

    cudaFuncSetAttribute(gemm_bf16<1>, cudaFuncAttributeMaxDynamicSharedMemorySize, GEMM_SMEM);
    cudaFuncSetAttribute(gemm_bf16<2>, cudaFuncAttributeMaxDynamicSharedMemorySize, GEMM_SMEM);
    cudaFuncSetAttribute(gemm_bf16<3>, cudaFuncAttributeMaxDynamicSharedMemorySize, GEMM_SMEM);
    cudaFuncSetAttribute(attn_mma_kernel, cudaFuncAttributeMaxDynamicSharedMemorySize, ATT_SMEM);

    // split all weights
    {
        int n4;
        n4 = NLAYER * QKVDIM * DMODEL / 4;
        split_kernel<<<(n4 + 255) / 256, 256>>>((const float4*)in_w,
            (__nv_bfloat162*)wih, (__nv_bfloat162*)wil, n4);
        n4 = NLAYER * DMODEL * DMODEL / 4;
        split_kernel<<<(n4 + 255) / 256, 256>>>((const float4*)out_w,
            (__nv_bfloat162*)woh, (__nv_bfloat162*)wol, n4);
        n4 = NLAYER * FFDIM * DMODEL / 4;
        split_kernel<<<(n4 + 255) / 256, 256>>>((const float4*)f1_w,
            (__nv_bfloat162*)w1h, (__nv_bfloat162*)w1l, n4);
        n4 = NLAYER * DMODEL * FFDIM / 4;
        split_kernel<<<(n4 + 255) / 256, 256>>>((const float4*)f2_w,
            (__nv_bfloat162*)w2h, (__nv_bfloat162*)w2l, n4);
    }

    // residual stream init
    {
        int n4 = ROWS * DMODEL / 4;
        copy_kernel<<<(n4 + 255) / 256, 256>>>((const float4*)x, (float4*)x_, n4);
    }

    dim3 blk256(256);
    for (int i = 0; i < NLAYER; i++) {
        __nv_bfloat16* iwh = wih + (size_t)i * QKVDIM * DMODEL;
        __nv_bfloat16* iwl = wil + (size_t)i * QKVDIM * DMODEL;
        __nv_bfloat16* owh = woh + (size_t)i * DMODEL * DMODEL;
        __nv_bfloat16* owl = wol + (size_t)i * DMODEL * DMODEL;
        __nv_bfloat16* f1h = w1h + (size_t)i * FFDIM * DMODEL;
        __nv_bfloat16* f1l = w1l + (size_t)i * FFDIM * DMODEL;
        __nv_bfloat16* f2h = w2h + (size_t)i * DMODEL * FFDIM;
        __nv_bfloat16* f2l = w2l + (size_t)i * DMODEL * FFDIM;
        const float* ib = in_b  + (size_t)i * QKVDIM;
        const float* ob = out_b + (size_t)i * DMODEL;
        const float* b1 = f1_b  + (size_t)i * FFDIM;
        const float* b2 = f2_b  + (size_t)i * DMODEL;

        ln_dual_kernel<<<ROWS, blk256>>>(x_, ln1_w + i * DMODEL, ln1_b + i * DMODEL, xnh, xnl);
        gemm_bf16<3><<<dim3(QKVDIM / 128, ROWS / 128), blk256, GEMM_SMEM>>>(
            xnh, xnl, iwh, iwl, ib, nullptr, nullptr, qkh, qkl, vth, vtl,
            ROWS, QKVDIM, DMODEL);
        attn_mma_kernel<<<dim3(TSEQ / 64, NHEAD, BATCH), 128, ATT_SMEM>>>(
            qkh, qkl, vth, vtl, atth, attl);
        gemm_bf16<2><<<dim3(DMODEL / 128, ROWS / 128), blk256, GEMM_SMEM>>>(
            atth, attl, owh, owl, ob, x_, x_, nullptr, nullptr, nullptr, nullptr,
            ROWS, DMODEL, DMODEL);
        ln_dual_kernel<<<ROWS, blk256>>>(x_, ln2_w + i * DMODEL, ln2_b + i * DMODEL, xnh, xnl);
        gemm_bf16<1><<<dim3(FFDIM / 128, ROWS / 128), blk256, GEMM_SMEM>>>(
            xnh, xnl, f1h, f1l, b1, nullptr, nullptr, hh, hl, nullptr, nullptr,
            ROWS, FFDIM, DMODEL);
        gemm_bf16<2><<<dim3(DMODEL / 128, ROWS / 128), blk256, GEMM_SMEM>>>(
            hh, hl, f2h, f2l, b2, x_, x_, nullptr, nullptr, nullptr, nullptr,
            ROWS, DMODEL, FFDIM);
    }
    ln_kernel<<<ROWS, blk256>>>(x_, final_w, final_b, (float*)d_out);
}

// round 12
// speedup vs baseline: 1.1043x; 1.1043x over previous
#include <cuda_runtime.h>
#include <cuda_bf16.h>
#include <math.h>
#include <stdint.h>

// Problem constants
#define TSEQ    2048
#define BATCH   2
#define DMODEL  1024
#define NHEAD   16
#define HEADDIM 64
#define FFDIM   4096
#define NLAYER  4
#define ROWS    (BATCH * TSEQ)          // 4096
#define QKVDIM  (3 * DMODEL)            // 3072
#define QKPITCH (2 * DMODEL)            // 2048 (Q cols 0..1023, K cols 1024..2047)

// -------------------- scratch (allocation-free) --------------------
__device__ float g_x  [ROWS * DMODEL];          // residual stream (fp32)
__device__ __nv_bfloat16 g_xn_h [ROWS * DMODEL];
__device__ __nv_bfloat16 g_xn_l [ROWS * DMODEL];
__device__ __nv_bfloat16 g_att_h[ROWS * DMODEL];
__device__ __nv_bfloat16 g_att_l[ROWS * DMODEL];
__device__ __nv_bfloat16 g_h_h  [ROWS * FFDIM];
__device__ __nv_bfloat16 g_h_l  [ROWS * FFDIM];
__device__ __nv_bfloat16 g_qk_h [ROWS * QKPITCH];
__device__ __nv_bfloat16 g_qk_l [ROWS * QKPITCH];
__device__ __nv_bfloat16 g_vt_h [BATCH * NHEAD * HEADDIM * TSEQ];
__device__ __nv_bfloat16 g_vt_l [BATCH * NHEAD * HEADDIM * TSEQ];
__device__ __nv_bfloat16 g_wi_h[NLAYER * QKVDIM * DMODEL];
__device__ __nv_bfloat16 g_wi_l[NLAYER * QKVDIM * DMODEL];
__device__ __nv_bfloat16 g_wo_h[NLAYER * DMODEL * DMODEL];
__device__ __nv_bfloat16 g_wo_l[NLAYER * DMODEL * DMODEL];
__device__ __nv_bfloat16 g_w1_h[NLAYER * FFDIM * DMODEL];
__device__ __nv_bfloat16 g_w1_l[NLAYER * FFDIM * DMODEL];
__device__ __nv_bfloat16 g_w2_h[NLAYER * DMODEL * FFDIM];
__device__ __nv_bfloat16 g_w2_l[NLAYER * DMODEL * FFDIM];

// -------------------- helpers --------------------
__device__ __forceinline__ void cp_async16(uint32_t smem, const void* g) {
    asm volatile("cp.async.cg.shared.global [%0], [%1], 16;\n" :: "r"(smem), "l"(g));
}
__device__ __forceinline__ void cp_commit() {
    asm volatile("cp.async.commit_group;\n" ::: "memory");
}
__device__ __forceinline__ void cp_wait0() {
    asm volatile("cp.async.wait_group 0;\n" ::: "memory");
}
__device__ __forceinline__ uint32_t smem_u32(const void* p) {
    return (uint32_t)__cvta_generic_to_shared(p);
}
__device__ __forceinline__ void split2(float v, __nv_bfloat16& h, __nv_bfloat16& l) {
    h = __float2bfloat16(v);
    l = __float2bfloat16(v - __bfloat162float(h));
}
__device__ __forceinline__ void splitpack(float a, float b, uint32_t& hi, uint32_t& lo) {
    __nv_bfloat16 ha, la, hb, lb;
    split2(a, ha, la); split2(b, hb, lb);
    __nv_bfloat162 ph; ph.x = ha; ph.y = hb;
    __nv_bfloat162 pl; pl.x = la; pl.y = lb;
    hi = *(uint32_t*)&ph; lo = *(uint32_t*)&pl;
}
__device__ __forceinline__ void mma_bf16(float* d, const uint32_t* a, uint32_t b0, uint32_t b1) {
    asm volatile(
        "mma.sync.aligned.m16n8k16.row.col.f32.bf16.bf16.f32 "
        "{%0,%1,%2,%3}, {%4,%5,%6,%7}, {%8,%9}, {%0,%1,%2,%3};\n"
        : "+f"(d[0]), "+f"(d[1]), "+f"(d[2]), "+f"(d[3])
        : "r"(a[0]), "r"(a[1]), "r"(a[2]), "r"(a[3]),
          "r"(b0), "r"(b1));
}

// -------------------- copy --------------------
__global__ void copy_kernel(const float4* __restrict__ in, float4* __restrict__ out, int n4) {
    int i = blockIdx.x * blockDim.x + threadIdx.x;
    if (i < n4) out[i] = in[i];
}

// -------------------- merged weight split (all 4 weight tensors, one launch) ------------
#define S0 (NLAYER * QKVDIM * DMODEL / 4)
#define S1 (NLAYER * DMODEL * DMODEL / 4)
#define S2 (NLAYER * FFDIM * DMODEL / 4)
#define S3 (NLAYER * DMODEL * FFDIM / 4)
#define SPLIT_TOTAL (S0 + S1 + S2 + S3)

__global__ void split_all_kernel(
    const float4* __restrict__ in0, const float4* __restrict__ in1,
    const float4* __restrict__ in2, const float4* __restrict__ in3,
    __nv_bfloat162* __restrict__ h0, __nv_bfloat162* __restrict__ l0p,
    __nv_bfloat162* __restrict__ h1, __nv_bfloat162* __restrict__ l1p,
    __nv_bfloat162* __restrict__ h2, __nv_bfloat162* __restrict__ l2p,
    __nv_bfloat162* __restrict__ h3, __nv_bfloat162* __restrict__ l3p)
{
    int i = blockIdx.x * blockDim.x + threadIdx.x;
    if (i >= SPLIT_TOTAL) return;
    const float4* in; __nv_bfloat162 *hi, *lo;
    int j = i;
    if (j < S0)                 { in = in0; hi = h0; lo = l0p; }
    else if ((j -= S0) < S1)    { in = in1; hi = h1; lo = l1p; }
    else if ((j -= S1) < S2)    { in = in2; hi = h2; lo = l2p; }
    else                        { j -= S2; in = in3; hi = h3; lo = l3p; }
    float4 v = in[j];
    uint32_t a0, b0, a1, b1;
    splitpack(v.x, v.y, a0, b0);
    splitpack(v.z, v.w, a1, b1);
    hi[j * 2 + 0] = *(__nv_bfloat162*)&a0; hi[j * 2 + 1] = *(__nv_bfloat162*)&a1;
    lo[j * 2 + 0] = *(__nv_bfloat162*)&b0; lo[j * 2 + 1] = *(__nv_bfloat162*)&b1;
}

// -------------------- layernorm (fp32 out — final) --------------------
__global__ void __launch_bounds__(256) ln_kernel(
    const float* __restrict__ in, const float* __restrict__ w,
    const float* __restrict__ b, float* __restrict__ out)
{
    int row = blockIdx.x;
    int tid = threadIdx.x;
    const float4* ip = (const float4*)(in + (size_t)row * DMODEL);
    float4 v = ip[tid];
    float s  = v.x + v.y + v.z + v.w;
    float sq = v.x * v.x + v.y * v.y + v.z * v.z + v.w * v.w;
    #pragma unroll
    for (int o = 16; o > 0; o >>= 1) {
        s  += __shfl_xor_sync(0xffffffffu, s,  o);
        sq += __shfl_xor_sync(0xffffffffu, sq, o);
    }
    __shared__ float reds[8], redq[8];
    int lane = tid & 31, wid = tid >> 5;
    if (lane == 0) { reds[wid] = s; redq[wid] = sq; }
    __syncthreads();
    float ts = 0.f, tq = 0.f;
    #pragma unroll
    for (int i = 0; i < 8; i++) { ts += reds[i]; tq += redq[i]; }
    float mean = ts * (1.0f / DMODEL);
    float var  = tq * (1.0f / DMODEL) - mean * mean;
    float rstd = rsqrtf(var + 1e-5f);
    float4 wv = ((const float4*)w)[tid];
    float4 bv = ((const float4*)b)[tid];
    float4 r;
    r.x = (v.x - mean) * rstd * wv.x + bv.x;
    r.y = (v.y - mean) * rstd * wv.y + bv.y;
    r.z = (v.z - mean) * rstd * wv.z + bv.z;
    r.w = (v.w - mean) * rstd * wv.w + bv.w;
    ((float4*)(out + (size_t)row * DMODEL))[tid] = r;
}

// -------------------- layernorm (dual-bf16 out) --------------------
__global__ void __launch_bounds__(256) ln_dual_kernel(
    const float* __restrict__ in, const float* __restrict__ w,
    const float* __restrict__ b,
    __nv_bfloat16* __restrict__ oh, __nv_bfloat16* __restrict__ ol)
{
    int row = blockIdx.x;
    int tid = threadIdx.x;
    const float4* ip = (const float4*)(in + (size_t)row * DMODEL);
    float4 v = ip[tid];
    float s  = v.x + v.y + v.z + v.w;
    float sq = v.x * v.x + v.y * v.y + v.z * v.z + v.w * v.w;
    #pragma unroll
    for (int o = 16; o > 0; o >>= 1) {
        s  += __shfl_xor_sync(0xffffffffu, s,  o);
        sq += __shfl_xor_sync(0xffffffffu, sq, o);
    }
    __shared__ float reds[8], redq[8];
    int lane = tid & 31, wid = tid >> 5;
    if (lane == 0) { reds[wid] = s; redq[wid] = sq; }
    __syncthreads();
    float ts = 0.f, tq = 0.f;
    #pragma unroll
    for (int i = 0; i < 8; i++) { ts += reds[i]; tq += redq[i]; }
    float mean = ts * (1.0f / DMODEL);
    float var  = tq * (1.0f / DMODEL) - mean * mean;
    float rstd = rsqrtf(var + 1e-5f);
    float4 wv = ((const float4*)w)[tid];
    float4 bv = ((const float4*)b)[tid];
    float r0 = (v.x - mean) * rstd * wv.x + bv.x;
    float r1 = (v.y - mean) * rstd * wv.y + bv.y;
    float r2 = (v.z - mean) * rstd * wv.z + bv.z;
    float r3 = (v.w - mean) * rstd * wv.w + bv.w;
    uint32_t ph0, pl0, ph1, pl1;
    splitpack(r0, r1, ph0, pl0);
    splitpack(r2, r3, ph1, pl1);
    size_t base = (size_t)row * DMODEL + tid * 4;
    *(uint32_t*)(oh + base)     = ph0;
    *(uint32_t*)(oh + base + 2) = ph1;
    *(uint32_t*)(ol + base)     = pl0;
    *(uint32_t*)(ol + base + 2) = pl1;
}

// -------------------- bf16 split-3 tensor-core GEMM (mma.sync m16n8k16) --------------------
// C[M,N] = A[M,K] @ W[N,K]^T + bias; A,W as hi/lo bf16 planes (K-major).
// Block 128x128, BK=32, 8 warps (4M x 2N), warp tile 32x64. Scalar LDS fragment
// loads (pitch-40 conflict-free) — proven faster than ldmatrix on this kernel (R11).
// EPI: 1 = bias+GELU -> dual-bf16 ; 2 = bias+residual -> fp32 ;
//      3 = bias -> QK dual planes + V transposed dual planes
#define GPITCH 40
#define A_ELE (128 * GPITCH)
#define W_ELE (128 * GPITCH)
#define STG_ELE (2 * A_ELE + 2 * W_ELE)
#define GEMM_SMEM (2 * STG_ELE * 2)           // 81920 bytes

template <int EPI>
__global__ void __launch_bounds__(256, 2) gemm_bf16(
    const __nv_bfloat16* __restrict__ Ah, const __nv_bfloat16* __restrict__ Al,
    const __nv_bfloat16* __restrict__ Wh, const __nv_bfloat16* __restrict__ Wl,
    const float* __restrict__ bias, const float* __restrict__ res,
    float* __restrict__ Cf, __nv_bfloat16* __restrict__ Ch, __nv_bfloat16* __restrict__ Cl,
    __nv_bfloat16* __restrict__ Vth, __nv_bfloat16* __restrict__ Vtl,
    int M, int N, int K)
{
    extern __shared__ __nv_bfloat16 smem[];
    uint32_t sbase = smem_u32(smem);

    int tid  = threadIdx.x;
    int lane = tid & 31;
    int wid  = tid >> 5;
    int warpM = (wid >> 1) * 32;
    int warpN = (wid & 1) * 64;
    int m0 = blockIdx.y * 128;
    int n0 = blockIdx.x * 128;

    int gr = lane >> 2;
    int gc = lane & 3;

    float acc[2][8][4];
    #pragma unroll
    for (int i = 0; i < 2; i++)
        #pragma unroll
        for (int j = 0; j < 8; j++)
            #pragma unroll
            for (int c = 0; c < 4; c++) acc[i][j][c] = 0.f;

    int KT = K >> 5;

    auto load_chunk = [&](int kt) {
        uint32_t sb = sbase + (uint32_t)(kt & 1) * STG_ELE * 2;
        int k0 = kt << 5;
        #pragma unroll
        for (int i = 0; i < 2; i++) {
            int idx = tid + i * 256;
            int row = idx >> 2;
            int k16 = idx & 3;
            uint32_t so = (uint32_t)(row * 80 + k16 * 16);
            size_t ga = (size_t)(m0 + row) * K + k0 + k16 * 8;
            size_t gw = (size_t)(n0 + row) * K + k0 + k16 * 8;
            cp_async16(sb + so, Ah + ga);
            cp_async16(sb + A_ELE * 2 + so, Al + ga);
            cp_async16(sb + 2 * A_ELE * 2 + so, Wh + gw);
            cp_async16(sb + (2 * A_ELE + W_ELE) * 2 + so, Wl + gw);
        }
        cp_commit();
    };

    load_chunk(0);

    for (int kt = 0; kt < KT; kt++) {
        cp_wait0();
        __syncthreads();
        if (kt + 1 < KT) load_chunk(kt + 1);

        const char* stg = (const char*)smem + (size_t)(kt & 1) * STG_ELE * 2;
        const char* sAh = stg;
        const char* sAl = stg + A_ELE * 2;
        const char* sWh = stg + 2 * A_ELE * 2;
        const char* sWl = stg + (2 * A_ELE + W_ELE) * 2;

        #pragma unroll
        for (int ks = 0; ks < 2; ks++) {
            int kby = ks * 32 + gc * 4;
            uint32_t ah[2][4], al[2][4];
            #pragma unroll
            for (int mt = 0; mt < 2; mt++) {
                int r = warpM + mt * 16 + gr;
                const char* p0 = sAh + r * 80 + kby;
                const char* p1 = sAh + (r + 8) * 80 + kby;
                ah[mt][0] = *(const uint32_t*)p0;
                ah[mt][1] = *(const uint32_t*)p1;
                ah[mt][2] = *(const uint32_t*)(p0 + 16);
                ah[mt][3] = *(const uint32_t*)(p1 + 16);
                const char* q0 = sAl + r * 80 + kby;
                const char* q1 = sAl + (r + 8) * 80 + kby;
                al[mt][0] = *(const uint32_t*)q0;
                al[mt][1] = *(const uint32_t*)q1;
                al[mt][2] = *(const uint32_t*)(q0 + 16);
                al[mt][3] = *(const uint32_t*)(q1 + 16);
            }
            #pragma unroll
            for (int nt = 0; nt < 8; nt++) {
                int c = warpN + nt * 8 + gr;
                uint32_t bh0, bh1, bl0, bl1;
                const char* p = sWh + c * 80 + kby;
                bh0 = *(const uint32_t*)p;
                bh1 = *(const uint32_t*)(p + 16);
                const char* q = sWl + c * 80 + kby;
                bl0 = *(const uint32_t*)q;
                bl1 = *(const uint32_t*)(q + 16);
                #pragma unroll
                for (int mt = 0; mt < 2; mt++) {
                    mma_bf16(acc[mt][nt], ah[mt], bh0, bh1);
                    mma_bf16(acc[mt][nt], ah[mt], bl0, bl1);
                    mma_bf16(acc[mt][nt], al[mt], bh0, bh1);
                }
            }
        }
        __syncthreads();
    }

    // ---- epilogue ----
    #pragma unroll
    for (int mt = 0; mt < 2; mt++) {
        int r0 = m0 + warpM + mt * 16 + gr;
        #pragma unroll
        for (int nt = 0; nt < 8; nt++) {
            int col = n0 + warpN + nt * 8 + 2 * gc;
            float b0 = bias[col], b1 = bias[col + 1];
            #pragma unroll
            for (int half = 0; half < 2; half++) {
                int row = r0 + half * 8;
                float v0 = acc[mt][nt][2 * half + 0] + b0;
                float v1 = acc[mt][nt][2 * half + 1] + b1;
                if (EPI == 1) {
                    v0 = 0.5f * v0 * (1.0f + erff(v0 * 0.70710678118654752f));
                    v1 = 0.5f * v1 * (1.0f + erff(v1 * 0.70710678118654752f));
                    uint32_t ph, pl;
                    splitpack(v0, v1, ph, pl);
                    size_t base = (size_t)row * N + col;
                    *(uint32_t*)(Ch + base) = ph;
                    *(uint32_t*)(Cl + base) = pl;
                } else if (EPI == 2) {
                    const float2 rv = *(const float2*)(res + (size_t)row * N + col);
                    v0 += rv.x; v1 += rv.y;
                    float2 o2; o2.x = v0; o2.y = v1;
                    *(float2*)(Cf + (size_t)row * N + col) = o2;
                } else {   // EPI == 3: QKV epilogue
                    if (col >= 2 * DMODEL) {
                        int c  = col - 2 * DMODEL;
                        int hh = c >> 6, d = c & 63;
                        int bb = row >> 11, t = row & (TSEQ - 1);
                        size_t vi = ((size_t)((bb * NHEAD + hh) * HEADDIM + d)) * TSEQ + t;
                        __nv_bfloat16 h0, l0v, h1, l1v;
                        split2(v0, h0, l0v); split2(v1, h1, l1v);
                        Vth[vi] = h0;        Vtl[vi] = l0v;
                        Vth[vi + TSEQ] = h1; Vtl[vi + TSEQ] = l1v;
                    } else {
                        uint32_t ph, pl;
                        splitpack(v0, v1, ph, pl);
                        size_t base = (size_t)row * QKPITCH + col;
                        *(uint32_t*)(Ch + base) = ph;
                        *(uint32_t*)(Cl + base) = pl;
                    }
                }
            }
        }
    }
}

// -------------------- mma flash attention (bf16 split-3, causal + ALiBi) --------------------
// Grid (T/64, H, B), 128 threads = 4 warps, each warp 16 query rows.
#define KV_PITCH_B 144
#define KV_TILE_B (64 * KV_PITCH_B)
#define ATT_STAGE (4 * KV_TILE_B)
#define ATT_SMEM  (2 * ATT_STAGE)              // 73728

__global__ void __launch_bounds__(128) attn_mma_kernel(
    const __nv_bfloat16* __restrict__ qkh, const __nv_bfloat16* __restrict__ qkl,
    const __nv_bfloat16* __restrict__ vth, const __nv_bfloat16* __restrict__ vtl,
    __nv_bfloat16* __restrict__ oh, __nv_bfloat16* __restrict__ ol)
{
    extern __shared__ char asmem[];
    uint32_t sbase = smem_u32(asmem);

    int b = blockIdx.z, h = blockIdx.y;
    int qt = gridDim.x - 1 - blockIdx.x;       // big tiles first
    int tid = threadIdx.x, lane = tid & 31, w = tid >> 5;
    int gr = lane >> 2, gc = lane & 3;

    int hcol = h * HEADDIM;
    int qrow0 = b * TSEQ + qt * 64;

    uint32_t qh[4][4], ql[4][4];
    {
        const __nv_bfloat16* qp  = qkh + (size_t)(qrow0 + w * 16) * QKPITCH + hcol;
        const __nv_bfloat16* qpl = qkl + (size_t)(qrow0 + w * 16) * QKPITCH + hcol;
        #pragma unroll
        for (int kc = 0; kc < 4; kc++) {
            int c = kc * 16 + 2 * gc;
            qh[kc][0] = *(const uint32_t*)(qp  + (size_t)gr * QKPITCH + c);
            qh[kc][1] = *(const uint32_t*)(qp  + (size_t)(gr + 8) * QKPITCH + c);
            qh[kc][2] = *(const uint32_t*)(qp  + (size_t)gr * QKPITCH + c + 8);
            qh[kc][3] = *(const uint32_t*)(qp  + (size_t)(gr + 8) * QKPITCH + c + 8);
            ql[kc][0] = *(const uint32_t*)(qpl + (size_t)gr * QKPITCH + c);
            ql[kc][1] = *(const uint32_t*)(qpl + (size_t)(gr + 8) * QKPITCH + c);
            ql[kc][2] = *(const uint32_t*)(qpl + (size_t)gr * QKPITCH + c + 8);
            ql[kc][3] = *(const uint32_t*)(qpl + (size_t)(gr + 8) * QKPITCH + c + 8);
        }
    }

    auto load_kv = [&](int kt, int s) {
        uint32_t sb = sbase + (uint32_t)s * ATT_STAGE;
        const __nv_bfloat16* Kh = qkh + (size_t)(b * TSEQ + kt * 64) * QKPITCH + DMODEL + hcol;
        const __nv_bfloat16* Kl = qkl + (size_t)(b * TSEQ + kt * 64) * QKPITCH + DMODEL + hcol;
        size_t vbase = (size_t)((b * NHEAD + h) * HEADDIM) * TSEQ + kt * 64;
        #pragma unroll
        for (int i = 0; i < 4; i++) {
            int idx = tid + i * 128;
            int r   = idx >> 3;
            int c16 = idx & 7;
            uint32_t so = (uint32_t)(r * KV_PITCH_B + c16 * 16);
            cp_async16(sb + so,                  Kh  + (size_t)r * QKPITCH + c16 * 8);
            cp_async16(sb + KV_TILE_B + so,      Kl  + (size_t)r * QKPITCH + c16 * 8);
            cp_async16(sb + 2 * KV_TILE_B + so,  vth + vbase + (size_t)r * TSEQ + c16 * 8);
            cp_async16(sb + 3 * KV_TILE_B + so,  vtl + vbase + (size_t)r * TSEQ + c16 * 8);
        }
        cp_commit();
    };

    float m0 = -INFINITY, m1 = -INFINITY, l0 = 0.f, l1 = 0.f;
    float acc_o[8][4];
    #pragma unroll
    for (int nt = 0; nt < 8; nt++)
        #pragma unroll
        for (int j = 0; j < 4; j++) acc_o[nt][j] = 0.f;

    float slope = exp2f(-0.5f * (float)(h + 1));
    int qpos0 = qt * 64 + w * 16 + gr;

    load_kv(0, 0);

    for (int kt = 0; kt <= qt; kt++) {
        int s = kt & 1;
        cp_wait0();
        __syncthreads();
        if (kt < qt) load_kv(kt + 1, s ^ 1);

        const char* Ksh = asmem + (size_t)s * ATT_STAGE;
        const char* Ksl = Ksh + KV_TILE_B;
        const char* Vsh = Ksh + 2 * KV_TILE_B;
        const char* Vsl = Ksh + 3 * KV_TILE_B;

        // ---- S = Q K^T ----
        float sacc[8][4];
        #pragma unroll
        for (int nt = 0; nt < 8; nt++)
            #pragma unroll
            for (int j = 0; j < 4; j++) sacc[nt][j] = 0.f;

        #pragma unroll
        for (int kc = 0; kc < 4; kc++) {
            int kby = kc * 32 + gc * 4;
            #pragma unroll
            for (int nt = 0; nt < 8; nt++) {
                int c = nt * 8 + gr;
                uint32_t bh0, bh1, bl0, bl1;
                const char* p = Ksh + c * KV_PITCH_B + kby;
                bh0 = *(const uint32_t*)p; bh1 = *(const uint32_t*)(p + 16);
                const char* q = Ksl + c * KV_PITCH_B + kby;
                bl0 = *(const uint32_t*)q; bl1 = *(const uint32_t*)(q + 16);
                mma_bf16(sacc[nt], qh[kc], bh0, bh1);
                mma_bf16(sacc[nt], qh[kc], bl0, bl1);
                mma_bf16(sacc[nt], ql[kc], bh0, bh1);
            }
        }

        // ---- mask + ALiBi + online softmax ----
        int kbase = kt * 64;
        float tmax0 = -INFINITY, tmax1 = -INFINITY;
        #pragma unroll
        for (int nt = 0; nt < 8; nt++) {
            #pragma unroll
            for (int j = 0; j < 4; j++) {
                int kp = kbase + nt * 8 + 2 * gc + (j & 1);
                int qp = qpos0 + ((j >> 1) << 3);
                float sv = (kp <= qp)
                    ? sacc[nt][j] * 0.125f + slope * (float)(kp - qp)
                    : -INFINITY;
                sacc[nt][j] = sv;
                if (j < 2) tmax0 = fmaxf(tmax0, sv);
                else       tmax1 = fmaxf(tmax1, sv);
            }
        }
        tmax0 = fmaxf(tmax0, __shfl_xor_sync(0xffffffffu, tmax0, 1));
        tmax0 = fmaxf(tmax0, __shfl_xor_sync(0xffffffffu, tmax0, 2));
        tmax1 = fmaxf(tmax1, __shfl_xor_sync(0xffffffffu, tmax1, 1));
        tmax1 = fmaxf(tmax1, __shfl_xor_sync(0xffffffffu, tmax1, 2));

        float nm0 = fmaxf(m0, tmax0);
        float nm1 = fmaxf(m1, tmax1);
        float corr0 = __expf(m0 - nm0);
        float corr1 = __expf(m1 - nm1);
        m0 = nm0; m1 = nm1;
        l0 *= corr0; l1 *= corr1;
        #pragma unroll
        for (int nt = 0; nt < 8; nt++) {
            acc_o[nt][0] *= corr0; acc_o[nt][1] *= corr0;
            acc_o[nt][2] *= corr1; acc_o[nt][3] *= corr1;
        }

        float ts0 = 0.f, ts1 = 0.f;
        #pragma unroll
        for (int nt = 0; nt < 8; nt++) {
            #pragma unroll
            for (int j = 0; j < 4; j++) {
                float p = __expf(sacc[nt][j] - ((j < 2) ? m0 : m1));
                sacc[nt][j] = p;
                if (j < 2) ts0 += p; else ts1 += p;
            }
        }
        ts0 += __shfl_xor_sync(0xffffffffu, ts0, 1);
        ts0 += __shfl_xor_sync(0xffffffffu, ts0, 2);
        ts1 += __shfl_xor_sync(0xffffffffu, ts1, 1);
        ts1 += __shfl_xor_sync(0xffffffffu, ts1, 2);
        l0 += ts0; l1 += ts1;

        // ---- O += P V ----
        #pragma unroll
        for (int kc = 0; kc < 4; kc++) {
            uint32_t ph[4], pl[4];
            splitpack(sacc[2 * kc][0],     sacc[2 * kc][1],     ph[0], pl[0]);
            splitpack(sacc[2 * kc][2],     sacc[2 * kc][3],     ph[1], pl[1]);
            splitpack(sacc[2 * kc + 1][0], sacc[2 * kc + 1][1], ph[2], pl[2]);
            splitpack(sacc[2 * kc + 1][2], sacc[2 * kc + 1][3], ph[3], pl[3]);
            int kby = kc * 32 + gc * 4;
            #pragma unroll
            for (int nt = 0; nt < 8; nt++) {
                int c = nt * 8 + gr;
                uint32_t bh0, bh1, bl0, bl1;
                const char* p = Vsh + c * KV_PITCH_B + kby;
                bh0 = *(const uint32_t*)p; bh1 = *(const uint32_t*)(p + 16);
                const char* q = Vsl + c * KV_PITCH_B + kby;
                bl0 = *(const uint32_t*)q; bl1 = *(const uint32_t*)(q + 16);
                mma_bf16(acc_o[nt], ph, bh0, bh1);
                mma_bf16(acc_o[nt], ph, bl0, bl1);
                mma_bf16(acc_o[nt], pl, bh0, bh1);
            }
        }
    }

    // ---- epilogue ----
    float inv0 = 1.0f / l0, inv1 = 1.0f / l1;
    int r0 = qrow0 + w * 16 + gr;
    #pragma unroll
    for (int nt = 0; nt < 8; nt++) {
        int col = hcol + nt * 8 + 2 * gc;
        uint32_t ph0, pl0, ph1, pl1;
        splitpack(acc_o[nt][0] * inv0, acc_o[nt][1] * inv0, ph0, pl0);
        splitpack(acc_o[nt][2] * inv1, acc_o[nt][3] * inv1, ph1, pl1);
        size_t b0 = (size_t)r0 * DMODEL + col;
        size_t b1 = (size_t)(r0 + 8) * DMODEL + col;
        *(uint32_t*)(oh + b0) = ph0; *(uint32_t*)(ol + b0) = pl0;
        *(uint32_t*)(oh + b1) = ph1; *(uint32_t*)(ol + b1) = pl1;
    }
}

// -------------------- launch --------------------
extern "C" void kernel_launch(void* const* d_in, const int* in_sizes, int n_in,
                              void* d_out, int out_size)
{
    const float* x        = (const float*)d_in[0];
    const float* in_w     = (const float*)d_in[1];
    const float* in_b     = (const float*)d_in[2];
    const float* out_w    = (const float*)d_in[3];
    const float* out_b    = (const float*)d_in[4];
    const float* f1_w     = (const float*)d_in[5];
    const float* f1_b     = (const float*)d_in[6];
    const float* f2_w     = (const float*)d_in[7];
    const float* f2_b     = (const float*)d_in[8];
    const float* ln1_w    = (const float*)d_in[9];
    const float* ln1_b    = (const float*)d_in[10];
    const float* ln2_w    = (const float*)d_in[11];
    const float* ln2_b    = (const float*)d_in[12];
    const float* final_w  = (const float*)d_in[13];
    const float* final_b  = (const float*)d_in[14];

    float *x_;
    __nv_bfloat16 *xnh, *xnl, *atth, *attl, *hh, *hl;
    __nv_bfloat16 *qkh, *qkl, *vth, *vtl;
    __nv_bfloat16 *wih, *wil, *woh, *wol, *w1h, *w1l, *w2h, *w2l;
    cudaGetSymbolAddress((void**)&x_,   g_x);
    cudaGetSymbolAddress((void**)&xnh,  g_xn_h);
    cudaGetSymbolAddress((void**)&xnl,  g_xn_l);
    cudaGetSymbolAddress((void**)&atth, g_att_h);
    cudaGetSymbolAddress((void**)&attl, g_att_l);
    cudaGetSymbolAddress((void**)&hh,   g_h_h);
    cudaGetSymbolAddress((void**)&hl,   g_h_l);
    cudaGetSymbolAddress((void**)&qkh,  g_qk_h);
    cudaGetSymbolAddress((void**)&qkl,  g_qk_l);
    cudaGetSymbolAddress((void**)&vth,  g_vt_h);
    cudaGetSymbolAddress((void**)&vtl,  g_vt_l);
    cudaGetSymbolAddress((void**)&wih,  g_wi_h);
    cudaGetSymbolAddress((void**)&wil,  g_wi_l);
    cudaGetSymbolAddress((void**)&woh,  g_wo_h);
    cudaGetSymbolAddress((void**)&wol,  g_wo_l);
    cudaGetSymbolAddress((void**)&w1h,  g_w1_h);
    cudaGetSymbolAddress((void**)&w1l,  g_w1_l);
    cudaGetSymbolAddress((void**)&w2h,  g_w2_h);
    cudaGetSymbolAddress((void**)&w2l,  g_w2_l);

    cudaFuncSetAttribute(gemm_bf16<1>, cudaFuncAttributeMaxDynamicSharedMemorySize, GEMM_SMEM);
    cudaFuncSetAttribute(gemm_bf16<2>, cudaFuncAttributeMaxDynamicSharedMemorySize, GEMM_SMEM);
    cudaFuncSetAttribute(gemm_bf16<3>, cudaFuncAttributeMaxDynamicSharedMemorySize, GEMM_SMEM);
    cudaFuncSetAttribute(attn_mma_kernel, cudaFuncAttributeMaxDynamicSharedMemorySize, ATT_SMEM);

    // split all weights in one launch
    split_all_kernel<<<(SPLIT_TOTAL + 255) / 256, 256>>>(
        (const float4*)in_w, (const float4*)out_w, (const float4*)f1_w, (const float4*)f2_w,
        (__nv_bfloat162*)wih, (__nv_bfloat162*)wil,
        (__nv_bfloat162*)woh, (__nv_bfloat162*)wol,
        (__nv_bfloat162*)w1h, (__nv_bfloat162*)w1l,
        (__nv_bfloat162*)w2h, (__nv_bfloat162*)w2l);

    // residual stream init
    {
        int n4 = ROWS * DMODEL / 4;
        copy_kernel<<<(n4 + 255) / 256, 256>>>((const float4*)x, (float4*)x_, n4);
    }

    dim3 blk256(256);
    for (int i = 0; i < NLAYER; i++) {
        __nv_bfloat16* iwh = wih + (size_t)i * QKVDIM * DMODEL;
        __nv_bfloat16* iwl = wil + (size_t)i * QKVDIM * DMODEL;
        __nv_bfloat16* owh = woh + (size_t)i * DMODEL * DMODEL;
        __nv_bfloat16* owl = wol + (size_t)i * DMODEL * DMODEL;
        __nv_bfloat16* f1h = w1h + (size_t)i * FFDIM * DMODEL;
        __nv_bfloat16* f1l = w1l + (size_t)i * FFDIM * DMODEL;
        __nv_bfloat16* f2h = w2h + (size_t)i * DMODEL * FFDIM;
        __nv_bfloat16* f2l = w2l + (size_t)i * DMODEL * FFDIM;
        const float* ib = in_b  + (size_t)i * QKVDIM;
        const float* ob = out_b + (size_t)i * DMODEL;
        const float* b1 = f1_b  + (size_t)i * FFDIM;
        const float* b2 = f2_b  + (size_t)i * DMODEL;

        ln_dual_kernel<<<ROWS, blk256>>>(x_, ln1_w + i * DMODEL, ln1_b + i * DMODEL, xnh, xnl);
        gemm_bf16<3><<<dim3(QKVDIM / 128, ROWS / 128), blk256, GEMM_SMEM>>>(
            xnh, xnl, iwh, iwl, ib, nullptr, nullptr, qkh, qkl, vth, vtl,
            ROWS, QKVDIM, DMODEL);
        attn_mma_kernel<<<dim3(TSEQ / 64, NHEAD, BATCH), 128, ATT_SMEM>>>(
            qkh, qkl, vth, vtl, atth, attl);
        gemm_bf16<2><<<dim3(DMODEL / 128, ROWS / 128), blk256, GEMM_SMEM>>>(
            atth, attl, owh, owl, ob, x_, x_, nullptr, nullptr, nullptr, nullptr,
            ROWS, DMODEL, DMODEL);
        ln_dual_kernel<<<ROWS, blk256>>>(x_, ln2_w + i * DMODEL, ln2_b + i * DMODEL, xnh, xnl);
        gemm_bf16<1><<<dim3(FFDIM / 128, ROWS / 128), blk256, GEMM_SMEM>>>(
            xnh, xnl, f1h, f1l, b1, nullptr, nullptr, hh, hl, nullptr, nullptr,
            ROWS, FFDIM, DMODEL);
        gemm_bf16<2><<<dim3(DMODEL / 128, ROWS / 128), blk256, GEMM_SMEM>>>(
            hh, hl, f2h, f2l, b2, x_, x_, nullptr, nullptr, nullptr, nullptr,
            ROWS, DMODEL, FFDIM);
    }
    ln_kernel<<<ROWS, blk256>>>(x_, final_w, final_b, (float*)d_out);
}

// round 13
// speedup vs baseline: 1.1092x; 1.0044x over previous
#include <cuda_runtime.h>
#include <cuda_bf16.h>
#include <math.h>
#include <stdint.h>

// Problem constants
#define TSEQ    2048
#define BATCH   2
#define DMODEL  1024
#define NHEAD   16
#define HEADDIM 64
#define FFDIM   4096
#define NLAYER  4
#define ROWS    (BATCH * TSEQ)          // 4096
#define QKVDIM  (3 * DMODEL)            // 3072
#define QKPITCH (2 * DMODEL)            // 2048

// -------------------- scratch (allocation-free) --------------------
__device__ float g_x  [ROWS * DMODEL];
__device__ __nv_bfloat16 g_xn_h [ROWS * DMODEL];
__device__ __nv_bfloat16 g_xn_l [ROWS * DMODEL];
__device__ __nv_bfloat16 g_att_h[ROWS * DMODEL];
__device__ __nv_bfloat16 g_att_l[ROWS * DMODEL];
__device__ __nv_bfloat16 g_h_h  [ROWS * FFDIM];
__device__ __nv_bfloat16 g_h_l  [ROWS * FFDIM];
__device__ __nv_bfloat16 g_qk_h [ROWS * QKPITCH];
__device__ __nv_bfloat16 g_qk_l [ROWS * QKPITCH];
__device__ __nv_bfloat16 g_vt_h [BATCH * NHEAD * HEADDIM * TSEQ];
__device__ __nv_bfloat16 g_vt_l [BATCH * NHEAD * HEADDIM * TSEQ];
__device__ __nv_bfloat16 g_wi_h[NLAYER * QKVDIM * DMODEL];
__device__ __nv_bfloat16 g_wi_l[NLAYER * QKVDIM * DMODEL];
__device__ __nv_bfloat16 g_wo_h[NLAYER * DMODEL * DMODEL];
__device__ __nv_bfloat16 g_wo_l[NLAYER * DMODEL * DMODEL];
__device__ __nv_bfloat16 g_w1_h[NLAYER * FFDIM * DMODEL];
__device__ __nv_bfloat16 g_w1_l[NLAYER * FFDIM * DMODEL];
__device__ __nv_bfloat16 g_w2_h[NLAYER * DMODEL * FFDIM];
__device__ __nv_bfloat16 g_w2_l[NLAYER * DMODEL * FFDIM];

// -------------------- helpers --------------------
__device__ __forceinline__ void cp_async16(uint32_t smem, const void* g) {
    asm volatile("cp.async.cg.shared.global [%0], [%1], 16;\n" :: "r"(smem), "l"(g));
}
__device__ __forceinline__ void cp_commit() {
    asm volatile("cp.async.commit_group;\n" ::: "memory");
}
__device__ __forceinline__ void cp_wait0() {
    asm volatile("cp.async.wait_group 0;\n" ::: "memory");
}
__device__ __forceinline__ uint32_t smem_u32(const void* p) {
    return (uint32_t)__cvta_generic_to_shared(p);
}
__device__ __forceinline__ void split2(float v, __nv_bfloat16& h, __nv_bfloat16& l) {
    h = __float2bfloat16(v);
    l = __float2bfloat16(v - __bfloat162float(h));
}
__device__ __forceinline__ void splitpack(float a, float b, uint32_t& hi, uint32_t& lo) {
    __nv_bfloat16 ha, la, hb, lb;
    split2(a, ha, la); split2(b, hb, lb);
    __nv_bfloat162 ph; ph.x = ha; ph.y = hb;
    __nv_bfloat162 pl; pl.x = la; pl.y = lb;
    hi = *(uint32_t*)&ph; lo = *(uint32_t*)&pl;
}
__device__ __forceinline__ void mma_bf16(float* d, const uint32_t* a, uint32_t b0, uint32_t b1) {
    asm volatile(
        "mma.sync.aligned.m16n8k16.row.col.f32.bf16.bf16.f32 "
        "{%0,%1,%2,%3}, {%4,%5,%6,%7}, {%8,%9}, {%0,%1,%2,%3};\n"
        : "+f"(d[0]), "+f"(d[1]), "+f"(d[2]), "+f"(d[3])
        : "r"(a[0]), "r"(a[1]), "r"(a[2]), "r"(a[3]),
          "r"(b0), "r"(b1));
}

// -------------------- copy --------------------
__global__ void copy_kernel(const float4* __restrict__ in, float4* __restrict__ out, int n4) {
    int i = blockIdx.x * blockDim.x + threadIdx.x;
    if (i < n4) out[i] = in[i];
}

// -------------------- merged weight split --------------------
#define S0 (NLAYER * QKVDIM * DMODEL / 4)
#define S1 (NLAYER * DMODEL * DMODEL / 4)
#define S2 (NLAYER * FFDIM * DMODEL / 4)
#define S3 (NLAYER * DMODEL * FFDIM / 4)
#define SPLIT_TOTAL (S0 + S1 + S2 + S3)

__global__ void split_all_kernel(
    const float4* __restrict__ in0, const float4* __restrict__ in1,
    const float4* __restrict__ in2, const float4* __restrict__ in3,
    __nv_bfloat162* __restrict__ h0, __nv_bfloat162* __restrict__ l0p,
    __nv_bfloat162* __restrict__ h1, __nv_bfloat162* __restrict__ l1p,
    __nv_bfloat162* __restrict__ h2, __nv_bfloat162* __restrict__ l2p,
    __nv_bfloat162* __restrict__ h3, __nv_bfloat162* __restrict__ l3p)
{
    int i = blockIdx.x * blockDim.x + threadIdx.x;
    if (i >= SPLIT_TOTAL) return;
    const float4* in; __nv_bfloat162 *hi, *lo;
    int j = i;
    if (j < S0)                 { in = in0; hi = h0; lo = l0p; }
    else if ((j -= S0) < S1)    { in = in1; hi = h1; lo = l1p; }
    else if ((j -= S1) < S2)    { in = in2; hi = h2; lo = l2p; }
    else                        { j -= S2; in = in3; hi = h3; lo = l3p; }
    float4 v = in[j];
    uint32_t a0, b0, a1, b1;
    splitpack(v.x, v.y, a0, b0);
    splitpack(v.z, v.w, a1, b1);
    hi[j * 2 + 0] = *(__nv_bfloat162*)&a0; hi[j * 2 + 1] = *(__nv_bfloat162*)&a1;
    lo[j * 2 + 0] = *(__nv_bfloat162*)&b0; lo[j * 2 + 1] = *(__nv_bfloat162*)&b1;
}

// -------------------- layernorm (fp32 out — final) --------------------
__global__ void __launch_bounds__(256) ln_kernel(
    const float* __restrict__ in, const float* __restrict__ w,
    const float* __restrict__ b, float* __restrict__ out)
{
    int row = blockIdx.x;
    int tid = threadIdx.x;
    const float4* ip = (const float4*)(in + (size_t)row * DMODEL);
    float4 v = ip[tid];
    float s  = v.x + v.y + v.z + v.w;
    float sq = v.x * v.x + v.y * v.y + v.z * v.z + v.w * v.w;
    #pragma unroll
    for (int o = 16; o > 0; o >>= 1) {
        s  += __shfl_xor_sync(0xffffffffu, s,  o);
        sq += __shfl_xor_sync(0xffffffffu, sq, o);
    }
    __shared__ float reds[8], redq[8];
    int lane = tid & 31, wid = tid >> 5;
    if (lane == 0) { reds[wid] = s; redq[wid] = sq; }
    __syncthreads();
    float ts = 0.f, tq = 0.f;
    #pragma unroll
    for (int i = 0; i < 8; i++) { ts += reds[i]; tq += redq[i]; }
    float mean = ts * (1.0f / DMODEL);
    float var  = tq * (1.0f / DMODEL) - mean * mean;
    float rstd = rsqrtf(var + 1e-5f);
    float4 wv = ((const float4*)w)[tid];
    float4 bv = ((const float4*)b)[tid];
    float4 r;
    r.x = (v.x - mean) * rstd * wv.x + bv.x;
    r.y = (v.y - mean) * rstd * wv.y + bv.y;
    r.z = (v.z - mean) * rstd * wv.z + bv.z;
    r.w = (v.w - mean) * rstd * wv.w + bv.w;
    ((float4*)(out + (size_t)row * DMODEL))[tid] = r;
}

// -------------------- layernorm (dual-bf16 out) --------------------
__global__ void __launch_bounds__(256) ln_dual_kernel(
    const float* __restrict__ in, const float* __restrict__ w,
    const float* __restrict__ b,
    __nv_bfloat16* __restrict__ oh, __nv_bfloat16* __restrict__ ol)
{
    int row = blockIdx.x;
    int tid = threadIdx.x;
    const float4* ip = (const float4*)(in + (size_t)row * DMODEL);
    float4 v = ip[tid];
    float s  = v.x + v.y + v.z + v.w;
    float sq = v.x * v.x + v.y * v.y + v.z * v.z + v.w * v.w;
    #pragma unroll
    for (int o = 16; o > 0; o >>= 1) {
        s  += __shfl_xor_sync(0xffffffffu, s,  o);
        sq += __shfl_xor_sync(0xffffffffu, sq, o);
    }
    __shared__ float reds[8], redq[8];
    int lane = tid & 31, wid = tid >> 5;
    if (lane == 0) { reds[wid] = s; redq[wid] = sq; }
    __syncthreads();
    float ts = 0.f, tq = 0.f;
    #pragma unroll
    for (int i = 0; i < 8; i++) { ts += reds[i]; tq += redq[i]; }
    float mean = ts * (1.0f / DMODEL);
    float var  = tq * (1.0f / DMODEL) - mean * mean;
    float rstd = rsqrtf(var + 1e-5f);
    float4 wv = ((const float4*)w)[tid];
    float4 bv = ((const float4*)b)[tid];
    float r0 = (v.x - mean) * rstd * wv.x + bv.x;
    float r1 = (v.y - mean) * rstd * wv.y + bv.y;
    float r2 = (v.z - mean) * rstd * wv.z + bv.z;
    float r3 = (v.w - mean) * rstd * wv.w + bv.w;
    uint32_t ph0, pl0, ph1, pl1;
    splitpack(r0, r1, ph0, pl0);
    splitpack(r2, r3, ph1, pl1);
    size_t base = (size_t)row * DMODEL + tid * 4;
    *(uint32_t*)(oh + base)     = ph0;
    *(uint32_t*)(oh + base + 2) = ph1;
    *(uint32_t*)(ol + base)     = pl0;
    *(uint32_t*)(ol + base + 2) = pl1;
}

// -------------------- bf16 split-3 tensor-core GEMM --------------------
// Block 128x128, BK=32, 8 warps (4M x 2N), warp tile 32x64.
// Term-major mma ordering over nt-pairs: same-accumulator reuse distance = 4 mma
// (breaks the 3-deep dependency chains that capped tensor pipe at 47%).
#define GPITCH 40
#define A_ELE (128 * GPITCH)
#define W_ELE (128 * GPITCH)
#define STG_ELE (2 * A_ELE + 2 * W_ELE)
#define GEMM_SMEM (2 * STG_ELE * 2)           // 81920 bytes

template <int EPI>
__global__ void __launch_bounds__(256, 2) gemm_bf16(
    const __nv_bfloat16* __restrict__ Ah, const __nv_bfloat16* __restrict__ Al,
    const __nv_bfloat16* __restrict__ Wh, const __nv_bfloat16* __restrict__ Wl,
    const float* __restrict__ bias, const float* __restrict__ res,
    float* __restrict__ Cf, __nv_bfloat16* __restrict__ Ch, __nv_bfloat16* __restrict__ Cl,
    __nv_bfloat16* __restrict__ Vth, __nv_bfloat16* __restrict__ Vtl,
    int M, int N, int K)
{
    extern __shared__ __nv_bfloat16 smem[];
    uint32_t sbase = smem_u32(smem);

    int tid  = threadIdx.x;
    int lane = tid & 31;
    int wid  = tid >> 5;
    int warpM = (wid >> 1) * 32;
    int warpN = (wid & 1) * 64;
    int m0 = blockIdx.y * 128;
    int n0 = blockIdx.x * 128;

    int gr = lane >> 2;
    int gc = lane & 3;

    float acc[2][8][4];
    #pragma unroll
    for (int i = 0; i < 2; i++)
        #pragma unroll
        for (int j = 0; j < 8; j++)
            #pragma unroll
            for (int c = 0; c < 4; c++) acc[i][j][c] = 0.f;

    int KT = K >> 5;

    auto load_chunk = [&](int kt) {
        uint32_t sb = sbase + (uint32_t)(kt & 1) * STG_ELE * 2;
        int k0 = kt << 5;
        #pragma unroll
        for (int i = 0; i < 2; i++) {
            int idx = tid + i * 256;
            int row = idx >> 2;
            int k16 = idx & 3;
            uint32_t so = (uint32_t)(row * 80 + k16 * 16);
            size_t ga = (size_t)(m0 + row) * K + k0 + k16 * 8;
            size_t gw = (size_t)(n0 + row) * K + k0 + k16 * 8;
            cp_async16(sb + so, Ah + ga);
            cp_async16(sb + A_ELE * 2 + so, Al + ga);
            cp_async16(sb + 2 * A_ELE * 2 + so, Wh + gw);
            cp_async16(sb + (2 * A_ELE + W_ELE) * 2 + so, Wl + gw);
        }
        cp_commit();
    };

    load_chunk(0);

    for (int kt = 0; kt < KT; kt++) {
        cp_wait0();
        __syncthreads();
        if (kt + 1 < KT) load_chunk(kt + 1);

        const char* stg = (const char*)smem + (size_t)(kt & 1) * STG_ELE * 2;
        const char* sAh = stg;
        const char* sAl = stg + A_ELE * 2;
        const char* sWh = stg + 2 * A_ELE * 2;
        const char* sWl = stg + (2 * A_ELE + W_ELE) * 2;

        #pragma unroll
        for (int ks = 0; ks < 2; ks++) {
            int kby = ks * 32 + gc * 4;
            uint32_t ah[2][4], al[2][4];
            #pragma unroll
            for (int mt = 0; mt < 2; mt++) {
                int r = warpM + mt * 16 + gr;
                const char* p0 = sAh + r * 80 + kby;
                const char* p1 = sAh + (r + 8) * 80 + kby;
                ah[mt][0] = *(const uint32_t*)p0;
                ah[mt][1] = *(const uint32_t*)p1;
                ah[mt][2] = *(const uint32_t*)(p0 + 16);
                ah[mt][3] = *(const uint32_t*)(p1 + 16);
                const char* q0 = sAl + r * 80 + kby;
                const char* q1 = sAl + (r + 8) * 80 + kby;
                al[mt][0] = *(const uint32_t*)q0;
                al[mt][1] = *(const uint32_t*)q1;
                al[mt][2] = *(const uint32_t*)(q0 + 16);
                al[mt][3] = *(const uint32_t*)(q1 + 16);
            }
            // process nt in pairs; term-major mma order -> dep distance 4
            #pragma unroll
            for (int np = 0; np < 4; np++) {
                int c0 = warpN + (2 * np) * 8 + gr;
                int c1 = warpN + (2 * np + 1) * 8 + gr;
                uint32_t b0h0, b0h1, b0l0, b0l1, b1h0, b1h1, b1l0, b1l1;
                {
                    const char* p = sWh + c0 * 80 + kby;
                    b0h0 = *(const uint32_t*)p; b0h1 = *(const uint32_t*)(p + 16);
                    const char* q = sWl + c0 * 80 + kby;
                    b0l0 = *(const uint32_t*)q; b0l1 = *(const uint32_t*)(q + 16);
                    const char* p2 = sWh + c1 * 80 + kby;
                    b1h0 = *(const uint32_t*)p2; b1h1 = *(const uint32_t*)(p2 + 16);
                    const char* q2 = sWl + c1 * 80 + kby;
                    b1l0 = *(const uint32_t*)q2; b1l1 = *(const uint32_t*)(q2 + 16);
                }
                float* a00 = acc[0][2 * np];
                float* a10 = acc[1][2 * np];
                float* a01 = acc[0][2 * np + 1];
                float* a11 = acc[1][2 * np + 1];
                // term 1: ah * bh
                mma_bf16(a00, ah[0], b0h0, b0h1);
                mma_bf16(a10, ah[1], b0h0, b0h1);
                mma_bf16(a01, ah[0], b1h0, b1h1);
                mma_bf16(a11, ah[1], b1h0, b1h1);
                // term 2: ah * bl
                mma_bf16(a00, ah[0], b0l0, b0l1);
                mma_bf16(a10, ah[1], b0l0, b0l1);
                mma_bf16(a01, ah[0], b1l0, b1l1);
                mma_bf16(a11, ah[1], b1l0, b1l1);
                // term 3: al * bh
                mma_bf16(a00, al[0], b0h0, b0h1);
                mma_bf16(a10, al[1], b0h0, b0h1);
                mma_bf16(a01, al[0], b1h0, b1h1);
                mma_bf16(a11, al[1], b1h0, b1h1);
            }
        }
        __syncthreads();
    }

    // ---- epilogue ----
    #pragma unroll
    for (int mt = 0; mt < 2; mt++) {
        int r0 = m0 + warpM + mt * 16 + gr;
        #pragma unroll
        for (int nt = 0; nt < 8; nt++) {
            int col = n0 + warpN + nt * 8 + 2 * gc;
            float b0 = bias[col], b1 = bias[col + 1];
            #pragma unroll
            for (int half = 0; half < 2; half++) {
                int row = r0 + half * 8;
                float v0 = acc[mt][nt][2 * half + 0] + b0;
                float v1 = acc[mt][nt][2 * half + 1] + b1;
                if (EPI == 1) {
                    v0 = 0.5f * v0 * (1.0f + erff(v0 * 0.70710678118654752f));
                    v1 = 0.5f * v1 * (1.0f + erff(v1 * 0.70710678118654752f));
                    uint32_t ph, pl;
                    splitpack(v0, v1, ph, pl);
                    size_t base = (size_t)row * N + col;
                    *(uint32_t*)(Ch + base) = ph;
                    *(uint32_t*)(Cl + base) = pl;
                } else if (EPI == 2) {
                    const float2 rv = *(const float2*)(res + (size_t)row * N + col);
                    v0 += rv.x; v1 += rv.y;
                    float2 o2; o2.x = v0; o2.y = v1;
                    *(float2*)(Cf + (size_t)row * N + col) = o2;
                } else {   // EPI == 3: QKV epilogue
                    if (col >= 2 * DMODEL) {
                        int c  = col - 2 * DMODEL;
                        int hh = c >> 6, d = c & 63;
                        int bb = row >> 11, t = row & (TSEQ - 1);
                        size_t vi = ((size_t)((bb * NHEAD + hh) * HEADDIM + d)) * TSEQ + t;
                        __nv_bfloat16 h0, l0v, h1, l1v;
                        split2(v0, h0, l0v); split2(v1, h1, l1v);
                        Vth[vi] = h0;        Vtl[vi] = l0v;
                        Vth[vi + TSEQ] = h1; Vtl[vi + TSEQ] = l1v;
                    } else {
                        uint32_t ph, pl;
                        splitpack(v0, v1, ph, pl);
                        size_t base = (size_t)row * QKPITCH + col;
                        *(uint32_t*)(Ch + base) = ph;
                        *(uint32_t*)(Cl + base) = pl;
                    }
                }
            }
        }
    }
}

// -------------------- mma flash attention (bf16 split-3, causal + ALiBi) --------------------
#define KV_PITCH_B 144
#define KV_TILE_B (64 * KV_PITCH_B)
#define ATT_STAGE (4 * KV_TILE_B)
#define ATT_SMEM  (2 * ATT_STAGE)              // 73728

__global__ void __launch_bounds__(128) attn_mma_kernel(
    const __nv_bfloat16* __restrict__ qkh, const __nv_bfloat16* __restrict__ qkl,
    const __nv_bfloat16* __restrict__ vth, const __nv_bfloat16* __restrict__ vtl,
    __nv_bfloat16* __restrict__ oh, __nv_bfloat16* __restrict__ ol)
{
    extern __shared__ char asmem[];
    uint32_t sbase = smem_u32(asmem);

    int b = blockIdx.z, h = blockIdx.y;
    int qt = gridDim.x - 1 - blockIdx.x;       // big tiles first
    int tid = threadIdx.x, lane = tid & 31, w = tid >> 5;
    int gr = lane >> 2, gc = lane & 3;

    int hcol = h * HEADDIM;
    int qrow0 = b * TSEQ + qt * 64;

    uint32_t qh[4][4], ql[4][4];
    {
        const __nv_bfloat16* qp  = qkh + (size_t)(qrow0 + w * 16) * QKPITCH + hcol;
        const __nv_bfloat16* qpl = qkl + (size_t)(qrow0 + w * 16) * QKPITCH + hcol;
        #pragma unroll
        for (int kc = 0; kc < 4; kc++) {
            int c = kc * 16 + 2 * gc;
            qh[kc][0] = *(const uint32_t*)(qp  + (size_t)gr * QKPITCH + c);
            qh[kc][1] = *(const uint32_t*)(qp  + (size_t)(gr + 8) * QKPITCH + c);
            qh[kc][2] = *(const uint32_t*)(qp  + (size_t)gr * QKPITCH + c + 8);
            qh[kc][3] = *(const uint32_t*)(qp  + (size_t)(gr + 8) * QKPITCH + c + 8);
            ql[kc][0] = *(const uint32_t*)(qpl + (size_t)gr * QKPITCH + c);
            ql[kc][1] = *(const uint32_t*)(qpl + (size_t)(gr + 8) * QKPITCH + c);
            ql[kc][2] = *(const uint32_t*)(qpl + (size_t)gr * QKPITCH + c + 8);
            ql[kc][3] = *(const uint32_t*)(qpl + (size_t)(gr + 8) * QKPITCH + c + 8);
        }
    }

    auto load_kv = [&](int kt, int s) {
        uint32_t sb = sbase + (uint32_t)s * ATT_STAGE;
        const __nv_bfloat16* Kh = qkh + (size_t)(b * TSEQ + kt * 64) * QKPITCH + DMODEL + hcol;
        const __nv_bfloat16* Kl = qkl + (size_t)(b * TSEQ + kt * 64) * QKPITCH + DMODEL + hcol;
        size_t vbase = (size_t)((b * NHEAD + h) * HEADDIM) * TSEQ + kt * 64;
        #pragma unroll
        for (int i = 0; i < 4; i++) {
            int idx = tid + i * 128;
            int r   = idx >> 3;
            int c16 = idx & 7;
            uint32_t so = (uint32_t)(r * KV_PITCH_B + c16 * 16);
            cp_async16(sb + so,                  Kh  + (size_t)r * QKPITCH + c16 * 8);
            cp_async16(sb + KV_TILE_B + so,      Kl  + (size_t)r * QKPITCH + c16 * 8);
            cp_async16(sb + 2 * KV_TILE_B + so,  vth + vbase + (size_t)r * TSEQ + c16 * 8);
            cp_async16(sb + 3 * KV_TILE_B + so,  vtl + vbase + (size_t)r * TSEQ + c16 * 8);
        }
        cp_commit();
    };

    float m0 = -INFINITY, m1 = -INFINITY, l0 = 0.f, l1 = 0.f;
    float acc_o[8][4];
    #pragma unroll
    for (int nt = 0; nt < 8; nt++)
        #pragma unroll
        for (int j = 0; j < 4; j++) acc_o[nt][j] = 0.f;

    float slope = exp2f(-0.5f * (float)(h + 1));
    int qpos0 = qt * 64 + w * 16 + gr;

    load_kv(0, 0);

    for (int kt = 0; kt <= qt; kt++) {
        int s = kt & 1;
        cp_wait0();
        __syncthreads();
        if (kt < qt) load_kv(kt + 1, s ^ 1);

        const char* Ksh = asmem + (size_t)s * ATT_STAGE;
        const char* Ksl = Ksh + KV_TILE_B;
        const char* Vsh = Ksh + 2 * KV_TILE_B;
        const char* Vsl = Ksh + 3 * KV_TILE_B;

        // ---- S = Q K^T (term-major over nt pairs) ----
        float sacc[8][4];
        #pragma unroll
        for (int nt = 0; nt < 8; nt++)
            #pragma unroll
            for (int j = 0; j < 4; j++) sacc[nt][j] = 0.f;

        #pragma unroll
        for (int kc = 0; kc < 4; kc++) {
            int kby = kc * 32 + gc * 4;
            #pragma unroll
            for (int np = 0; np < 4; np++) {
                int c0 = (2 * np) * 8 + gr;
                int c1 = (2 * np + 1) * 8 + gr;
                uint32_t b0h0, b0h1, b0l0, b0l1, b1h0, b1h1, b1l0, b1l1;
                {
                    const char* p = Ksh + c0 * KV_PITCH_B + kby;
                    b0h0 = *(const uint32_t*)p; b0h1 = *(const uint32_t*)(p + 16);
                    const char* q = Ksl + c0 * KV_PITCH_B + kby;
                    b0l0 = *(const uint32_t*)q; b0l1 = *(const uint32_t*)(q + 16);
                    const char* p2 = Ksh + c1 * KV_PITCH_B + kby;
                    b1h0 = *(const uint32_t*)p2; b1h1 = *(const uint32_t*)(p2 + 16);
                    const char* q2 = Ksl + c1 * KV_PITCH_B + kby;
                    b1l0 = *(const uint32_t*)q2; b1l1 = *(const uint32_t*)(q2 + 16);
                }
                float* s0 = sacc[2 * np];
                float* s1 = sacc[2 * np + 1];
                mma_bf16(s0, qh[kc], b0h0, b0h1);
                mma_bf16(s1, qh[kc], b1h0, b1h1);
                mma_bf16(s0, qh[kc], b0l0, b0l1);
                mma_bf16(s1, qh[kc], b1l0, b1l1);
                mma_bf16(s0, ql[kc], b0h0, b0h1);
                mma_bf16(s1, ql[kc], b1h0, b1h1);
            }
        }

        // ---- mask + ALiBi + online softmax ----
        int kbase = kt * 64;
        float tmax0 = -INFINITY, tmax1 = -INFINITY;
        #pragma unroll
        for (int nt = 0; nt < 8; nt++) {
            #pragma unroll
            for (int j = 0; j < 4; j++) {
                int kp = kbase + nt * 8 + 2 * gc + (j & 1);
                int qp = qpos0 + ((j >> 1) << 3);
                float sv = (kp <= qp)
                    ? sacc[nt][j] * 0.125f + slope * (float)(kp - qp)
                    : -INFINITY;
                sacc[nt][j] = sv;
                if (j < 2) tmax0 = fmaxf(tmax0, sv);
                else       tmax1 = fmaxf(tmax1, sv);
            }
        }
        tmax0 = fmaxf(tmax0, __shfl_xor_sync(0xffffffffu, tmax0, 1));
        tmax0 = fmaxf(tmax0, __shfl_xor_sync(0xffffffffu, tmax0, 2));
        tmax1 = fmaxf(tmax1, __shfl_xor_sync(0xffffffffu, tmax1, 1));
        tmax1 = fmaxf(tmax1, __shfl_xor_sync(0xffffffffu, tmax1, 2));

        float nm0 = fmaxf(m0, tmax0);
        float nm1 = fmaxf(m1, tmax1);
        float corr0 = __expf(m0 - nm0);
        float corr1 = __expf(m1 - nm1);
        m0 = nm0; m1 = nm1;
        l0 *= corr0; l1 *= corr1;
        #pragma unroll
        for (int nt = 0; nt < 8; nt++) {
            acc_o[nt][0] *= corr0; acc_o[nt][1] *= corr0;
            acc_o[nt][2] *= corr1; acc_o[nt][3] *= corr1;
        }

        float ts0 = 0.f, ts1 = 0.f;
        #pragma unroll
        for (int nt = 0; nt < 8; nt++) {
            #pragma unroll
            for (int j = 0; j < 4; j++) {
                float p = __expf(sacc[nt][j] - ((j < 2) ? m0 : m1));
                sacc[nt][j] = p;
                if (j < 2) ts0 += p; else ts1 += p;
            }
        }
        ts0 += __shfl_xor_sync(0xffffffffu, ts0, 1);
        ts0 += __shfl_xor_sync(0xffffffffu, ts0, 2);
        ts1 += __shfl_xor_sync(0xffffffffu, ts1, 1);
        ts1 += __shfl_xor_sync(0xffffffffu, ts1, 2);
        l0 += ts0; l1 += ts1;

        // ---- O += P V (term-major over nt pairs) ----
        #pragma unroll
        for (int kc = 0; kc < 4; kc++) {
            uint32_t ph[4], pl[4];
            splitpack(sacc[2 * kc][0],     sacc[2 * kc][1],     ph[0], pl[0]);
            splitpack(sacc[2 * kc][2],     sacc[2 * kc][3],     ph[1], pl[1]);
            splitpack(sacc[2 * kc + 1][0], sacc[2 * kc + 1][1], ph[2], pl[2]);
            splitpack(sacc[2 * kc + 1][2], sacc[2 * kc + 1][3], ph[3], pl[3]);
            int kby = kc * 32 + gc * 4;
            #pragma unroll
            for (int np = 0; np < 4; np++) {
                int c0 = (2 * np) * 8 + gr;
                int c1 = (2 * np + 1) * 8 + gr;
                uint32_t b0h0, b0h1, b0l0, b0l1, b1h0, b1h1, b1l0, b1l1;
                {
                    const char* p = Vsh + c0 * KV_PITCH_B + kby;
                    b0h0 = *(const uint32_t*)p; b0h1 = *(const uint32_t*)(p + 16);
                    const char* q = Vsl + c0 * KV_PITCH_B + kby;
                    b0l0 = *(const uint32_t*)q; b0l1 = *(const uint32_t*)(q + 16);
                    const char* p2 = Vsh + c1 * KV_PITCH_B + kby;
                    b1h0 = *(const uint32_t*)p2; b1h1 = *(const uint32_t*)(p2 + 16);
                    const char* q2 = Vsl + c1 * KV_PITCH_B + kby;
                    b1l0 = *(const uint32_t*)q2; b1l1 = *(const uint32_t*)(q2 + 16);
                }
                float* o0 = acc_o[2 * np];
                float* o1 = acc_o[2 * np + 1];
                mma_bf16(o0, ph, b0h0, b0h1);
                mma_bf16(o1, ph, b1h0, b1h1);
                mma_bf16(o0, ph, b0l0, b0l1);
                mma_bf16(o1, ph, b1l0, b1l1);
                mma_bf16(o0, pl, b0h0, b0h1);
                mma_bf16(o1, pl, b1h0, b1h1);
            }
        }
    }

    // ---- epilogue ----
    float inv0 = 1.0f / l0, inv1 = 1.0f / l1;
    int r0 = qrow0 + w * 16 + gr;
    #pragma unroll
    for (int nt = 0; nt < 8; nt++) {
        int col = hcol + nt * 8 + 2 * gc;
        uint32_t ph0, pl0, ph1, pl1;
        splitpack(acc_o[nt][0] * inv0, acc_o[nt][1] * inv0, ph0, pl0);
        splitpack(acc_o[nt][2] * inv1, acc_o[nt][3] * inv1, ph1, pl1);
        size_t b0 = (size_t)r0 * DMODEL + col;
        size_t b1 = (size_t)(r0 + 8) * DMODEL + col;
        *(uint32_t*)(oh + b0) = ph0; *(uint32_t*)(ol + b0) = pl0;
        *(uint32_t*)(oh + b1) = ph1; *(uint32_t*)(ol + b1) = pl1;
    }
}

// -------------------- launch --------------------
extern "C" void kernel_launch(void* const* d_in, const int* in_sizes, int n_in,
                              void* d_out, int out_size)
{
    const float* x        = (const float*)d_in[0];
    const float* in_w     = (const float*)d_in[1];
    const float* in_b     = (const float*)d_in[2];
    const float* out_w    = (const float*)d_in[3];
    const float* out_b    = (const float*)d_in[4];
    const float* f1_w     = (const float*)d_in[5];
    const float* f1_b     = (const float*)d_in[6];
    const float* f2_w     = (const float*)d_in[7];
    const float* f2_b     = (const float*)d_in[8];
    const float* ln1_w    = (const float*)d_in[9];
    const float* ln1_b    = (const float*)d_in[10];
    const float* ln2_w    = (const float*)d_in[11];
    const float* ln2_b    = (const float*)d_in[12];
    const float* final_w  = (const float*)d_in[13];
    const float* final_b  = (const float*)d_in[14];

    float *x_;
    __nv_bfloat16 *xnh, *xnl, *atth, *attl, *hh, *hl;
    __nv_bfloat16 *qkh, *qkl, *vth, *vtl;
    __nv_bfloat16 *wih, *wil, *woh, *wol, *w1h, *w1l, *w2h, *w2l;
    cudaGetSymbolAddress((void**)&x_,   g_x);
    cudaGetSymbolAddress((void**)&xnh,  g_xn_h);
    cudaGetSymbolAddress((void**)&xnl,  g_xn_l);
    cudaGetSymbolAddress((void**)&atth, g_att_h);
    cudaGetSymbolAddress((void**)&attl, g_att_l);
    cudaGetSymbolAddress((void**)&hh,   g_h_h);
    cudaGetSymbolAddress((void**)&hl,   g_h_l);
    cudaGetSymbolAddress((void**)&qkh,  g_qk_h);
    cudaGetSymbolAddress((void**)&qkl,  g_qk_l);
    cudaGetSymbolAddress((void**)&vth,  g_vt_h);
    cudaGetSymbolAddress((void**)&vtl,  g_vt_l);
    cudaGetSymbolAddress((void**)&wih,  g_wi_h);
    cudaGetSymbolAddress((void**)&wil,  g_wi_l);
    cudaGetSymbolAddress((void**)&woh,  g_wo_h);
    cudaGetSymbolAddress((void**)&wol,  g_wo_l);
    cudaGetSymbolAddress((void**)&w1h,  g_w1_h);
    cudaGetSymbolAddress((void**)&w1l,  g_w1_l);
    cudaGetSymbolAddress((void**)&w2h,  g_w2_h);
    cudaGetSymbolAddress((void**)&w2l,  g_w2_l);

    cudaFuncSetAttribute(gemm_bf16<1>, cudaFuncAttributeMaxDynamicSharedMemorySize, GEMM_SMEM);
    cudaFuncSetAttribute(gemm_bf16<2>, cudaFuncAttributeMaxDynamicSharedMemorySize, GEMM_SMEM);
    cudaFuncSetAttribute(gemm_bf16<3>, cudaFuncAttributeMaxDynamicSharedMemorySize, GEMM_SMEM);
    cudaFuncSetAttribute(attn_mma_kernel, cudaFuncAttributeMaxDynamicSharedMemorySize, ATT_SMEM);

    split_all_kernel<<<(SPLIT_TOTAL + 255) / 256, 256>>>(
        (const float4*)in_w, (const float4*)out_w, (const float4*)f1_w, (const float4*)f2_w,
        (__nv_bfloat162*)wih, (__nv_bfloat162*)wil,
        (__nv_bfloat162*)woh, (__nv_bfloat162*)wol,
        (__nv_bfloat162*)w1h, (__nv_bfloat162*)w1l,
        (__nv_bfloat162*)w2h, (__nv_bfloat162*)w2l);

    {
        int n4 = ROWS * DMODEL / 4;
        copy_kernel<<<(n4 + 255) / 256, 256>>>((const float4*)x, (float4*)x_, n4);
    }

    dim3 blk256(256);
    for (int i = 0; i < NLAYER; i++) {
        __nv_bfloat16* iwh = wih + (size_t)i * QKVDIM * DMODEL;
        __nv_bfloat16* iwl = wil + (size_t)i * QKVDIM * DMODEL;
        __nv_bfloat16* owh = woh + (size_t)i * DMODEL * DMODEL;
        __nv_bfloat16* owl = wol + (size_t)i * DMODEL * DMODEL;
        __nv_bfloat16* f1h = w1h + (size_t)i * FFDIM * DMODEL;
        __nv_bfloat16* f1l = w1l + (size_t)i * FFDIM * DMODEL;
        __nv_bfloat16* f2h = w2h + (size_t)i * DMODEL * FFDIM;
        __nv_bfloat16* f2l = w2l + (size_t)i * DMODEL * FFDIM;
        const float* ib = in_b  + (size_t)i * QKVDIM;
        const float* ob = out_b + (size_t)i * DMODEL;
        const float* b1 = f1_b  + (size_t)i * FFDIM;
        const float* b2 = f2_b  + (size_t)i * DMODEL;

        ln_dual_kernel<<<ROWS, blk256>>>(x_, ln1_w + i * DMODEL, ln1_b + i * DMODEL, xnh, xnl);
        gemm_bf16<3><<<dim3(QKVDIM / 128, ROWS / 128), blk256, GEMM_SMEM>>>(
            xnh, xnl, iwh, iwl, ib, nullptr, nullptr, qkh, qkl, vth, vtl,
            ROWS, QKVDIM, DMODEL);
        attn_mma_kernel<<<dim3(TSEQ / 64, NHEAD, BATCH), 128, ATT_SMEM>>>(
            qkh, qkl, vth, vtl, atth, attl);
        gemm_bf16<2><<<dim3(DMODEL / 128, ROWS / 128), blk256, GEMM_SMEM>>>(
            atth, attl, owh, owl, ob, x_, x_, nullptr, nullptr, nullptr, nullptr,
            ROWS, DMODEL, DMODEL);
        ln_dual_kernel<<<ROWS, blk256>>>(x_, ln2_w + i * DMODEL, ln2_b + i * DMODEL, xnh, xnl);
        gemm_bf16<1><<<dim3(FFDIM / 128, ROWS / 128), blk256, GEMM_SMEM>>>(
            xnh, xnl, f1h, f1l, b1, nullptr, nullptr, hh, hl, nullptr, nullptr,
            ROWS, FFDIM, DMODEL);
        gemm_bf16<2><<<dim3(DMODEL / 128, ROWS / 128), blk256, GEMM_SMEM>>>(
            hh, hl, f2h, f2l, b2, x_, x_, nullptr, nullptr, nullptr, nullptr,
            ROWS, DMODEL, FFDIM);
    }
    ln_kernel<<<ROWS, blk256>>>(x_, final_w, final_b, (float*)d_out);
}

// round 15
// speedup vs baseline: 1.4960x; 1.3487x over previous
#include <cuda_runtime.h>
#include <cuda_fp16.h>
#include <math.h>
#include <stdint.h>

// Problem constants
#define TSEQ    2048
#define BATCH   2
#define DMODEL  1024
#define NHEAD   16
#define HEADDIM 64
#define FFDIM   4096
#define NLAYER  4
#define ROWS    (BATCH * TSEQ)          // 4096
#define QKVDIM  (3 * DMODEL)            // 3072
#define QKPITCH (2 * DMODEL)            // 2048

// -------------------- scratch (allocation-free) --------------------
__device__ float g_x  [ROWS * DMODEL];          // residual stream fp32
// single-plane fp16 activations (A-side of matmuls)
__device__ __half g_xn [ROWS * DMODEL];
__device__ __half g_att[ROWS * DMODEL];
__device__ __half g_h  [ROWS * FFDIM];
// Q(hi) + K(hi) packed plane, K(lo) plane, V transposed dual planes
__device__ __half g_qk_h[ROWS * QKPITCH];
__device__ __half g_qk_l[ROWS * QKPITCH];
__device__ __half g_vt_h[BATCH * NHEAD * HEADDIM * TSEQ];
__device__ __half g_vt_l[BATCH * NHEAD * HEADDIM * TSEQ];
// dual fp16 weight planes
__device__ __half g_wi_h[NLAYER * QKVDIM * DMODEL];
__device__ __half g_wi_l[NLAYER * QKVDIM * DMODEL];
__device__ __half g_wo_h[NLAYER * DMODEL * DMODEL];
__device__ __half g_wo_l[NLAYER * DMODEL * DMODEL];
__device__ __half g_w1_h[NLAYER * FFDIM * DMODEL];
__device__ __half g_w1_l[NLAYER * FFDIM * DMODEL];
__device__ __half g_w2_h[NLAYER * DMODEL * FFDIM];
__device__ __half g_w2_l[NLAYER * DMODEL * FFDIM];

// -------------------- helpers --------------------
__device__ __forceinline__ void cp_async16(uint32_t smem, const void* g) {
    asm volatile("cp.async.cg.shared.global [%0], [%1], 16;\n" :: "r"(smem), "l"(g));
}
__device__ __forceinline__ void cp_commit() {
    asm volatile("cp.async.commit_group;\n" ::: "memory");
}
__device__ __forceinline__ void cp_wait0() {
    asm volatile("cp.async.wait_group 0;\n" ::: "memory");
}
__device__ __forceinline__ uint32_t smem_u32(const void* p) {
    return (uint32_t)__cvta_generic_to_shared(p);
}
__device__ __forceinline__ void split2h(float v, __half& h, __half& l) {
    h = __float2half_rn(v);
    l = __float2half_rn(v - __half2float(h));
}
__device__ __forceinline__ uint32_t packh(float a, float b) {
    __half2 t = __floats2half2_rn(a, b);
    return *(uint32_t*)&t;
}
__device__ __forceinline__ void splitpackh(float a, float b, uint32_t& hi, uint32_t& lo) {
    __half ha, la, hb, lb;
    split2h(a, ha, la); split2h(b, hb, lb);
    __half2 ph; ph.x = ha; ph.y = hb;
    __half2 pl; pl.x = la; pl.y = lb;
    hi = *(uint32_t*)&ph; lo = *(uint32_t*)&pl;
}
__device__ __forceinline__ void mma_f16(float* d, const uint32_t* a, uint32_t b0, uint32_t b1) {
    asm volatile(
        "mma.sync.aligned.m16n8k16.row.col.f32.f16.f16.f32 "
        "{%0,%1,%2,%3}, {%4,%5,%6,%7}, {%8,%9}, {%0,%1,%2,%3};\n"
        : "+f"(d[0]), "+f"(d[1]), "+f"(d[2]), "+f"(d[3])
        : "r"(a[0]), "r"(a[1]), "r"(a[2]), "r"(a[3]),
          "r"(b0), "r"(b1));
}

// -------------------- copy --------------------
__global__ void copy_kernel(const float4* __restrict__ in, float4* __restrict__ out, int n4) {
    int i = blockIdx.x * blockDim.x + threadIdx.x;
    if (i < n4) out[i] = in[i];
}

// -------------------- merged weight split (fp32 -> dual fp16) --------------------
#define S0 (NLAYER * QKVDIM * DMODEL / 4)
#define S1 (NLAYER * DMODEL * DMODEL / 4)
#define S2 (NLAYER * FFDIM * DMODEL / 4)
#define S3 (NLAYER * DMODEL * FFDIM / 4)
#define SPLIT_TOTAL (S0 + S1 + S2 + S3)

__global__ void split_all_kernel(
    const float4* __restrict__ in0, const float4* __restrict__ in1,
    const float4* __restrict__ in2, const float4* __restrict__ in3,
    uint32_t* __restrict__ h0, uint32_t* __restrict__ l0p,
    uint32_t* __restrict__ h1, uint32_t* __restrict__ l1p,
    uint32_t* __restrict__ h2, uint32_t* __restrict__ l2p,
    uint32_t* __restrict__ h3, uint32_t* __restrict__ l3p)
{
    int i = blockIdx.x * blockDim.x + threadIdx.x;
    if (i >= SPLIT_TOTAL) return;
    const float4* in; uint32_t *hi, *lo;
    int j = i;
    if (j < S0)                 { in = in0; hi = h0; lo = l0p; }
    else if ((j -= S0) < S1)    { in = in1; hi = h1; lo = l1p; }
    else if ((j -= S1) < S2)    { in = in2; hi = h2; lo = l2p; }
    else                        { j -= S2; in = in3; hi = h3; lo = l3p; }
    float4 v = in[j];
    uint32_t a0, b0, a1, b1;
    splitpackh(v.x, v.y, a0, b0);
    splitpackh(v.z, v.w, a1, b1);
    hi[j * 2 + 0] = a0; hi[j * 2 + 1] = a1;
    lo[j * 2 + 0] = b0; lo[j * 2 + 1] = b1;
}

// -------------------- layernorm (fp32 out — final) --------------------
__global__ void __launch_bounds__(256) ln_kernel(
    const float* __restrict__ in, const float* __restrict__ w,
    const float* __restrict__ b, float* __restrict__ out)
{
    int row = blockIdx.x;
    int tid = threadIdx.x;
    const float4* ip = (const float4*)(in + (size_t)row * DMODEL);
    float4 v = ip[tid];
    float s  = v.x + v.y + v.z + v.w;
    float sq = v.x * v.x + v.y * v.y + v.z * v.z + v.w * v.w;
    #pragma unroll
    for (int o = 16; o > 0; o >>= 1) {
        s  += __shfl_xor_sync(0xffffffffu, s,  o);
        sq += __shfl_xor_sync(0xffffffffu, sq, o);
    }
    __shared__ float reds[8], redq[8];
    int lane = tid & 31, wid = tid >> 5;
    if (lane == 0) { reds[wid] = s; redq[wid] = sq; }
    __syncthreads();
    float ts = 0.f, tq = 0.f;
    #pragma unroll
    for (int i = 0; i < 8; i++) { ts += reds[i]; tq += redq[i]; }
    float mean = ts * (1.0f / DMODEL);
    float var  = tq * (1.0f / DMODEL) - mean * mean;
    float rstd = rsqrtf(var + 1e-5f);
    float4 wv = ((const float4*)w)[tid];
    float4 bv = ((const float4*)b)[tid];
    float4 r;
    r.x = (v.x - mean) * rstd * wv.x + bv.x;
    r.y = (v.y - mean) * rstd * wv.y + bv.y;
    r.z = (v.z - mean) * rstd * wv.z + bv.z;
    r.w = (v.w - mean) * rstd * wv.w + bv.w;
    ((float4*)(out + (size_t)row * DMODEL))[tid] = r;
}

// -------------------- layernorm (fp16 out) --------------------
__global__ void __launch_bounds__(256) ln_half_kernel(
    const float* __restrict__ in, const float* __restrict__ w,
    const float* __restrict__ b, __half* __restrict__ oh)
{
    int row = blockIdx.x;
    int tid = threadIdx.x;
    const float4* ip = (const float4*)(in + (size_t)row * DMODEL);
    float4 v = ip[tid];
    float s  = v.x + v.y + v.z + v.w;
    float sq = v.x * v.x + v.y * v.y + v.z * v.z + v.w * v.w;
    #pragma unroll
    for (int o = 16; o > 0; o >>= 1) {
        s  += __shfl_xor_sync(0xffffffffu, s,  o);
        sq += __shfl_xor_sync(0xffffffffu, sq, o);
    }
    __shared__ float reds[8], redq[8];
    int lane = tid & 31, wid = tid >> 5;
    if (lane == 0) { reds[wid] = s; redq[wid] = sq; }
    __syncthreads();
    float ts = 0.f, tq = 0.f;
    #pragma unroll
    for (int i = 0; i < 8; i++) { ts += reds[i]; tq += redq[i]; }
    float mean = ts * (1.0f / DMODEL);
    float var  = tq * (1.0f / DMODEL) - mean * mean;
    float rstd = rsqrtf(var + 1e-5f);
    float4 wv = ((const float4*)w)[tid];
    float4 bv = ((const float4*)b)[tid];
    float r0 = (v.x - mean) * rstd * wv.x + bv.x;
    float r1 = (v.y - mean) * rstd * wv.y + bv.y;
    float r2 = (v.z - mean) * rstd * wv.z + bv.z;
    float r3 = (v.w - mean) * rstd * wv.w + bv.w;
    size_t base = (size_t)row * DMODEL + tid * 4;
    *(uint32_t*)(oh + base)     = packh(r0, r1);
    *(uint32_t*)(oh + base + 2) = packh(r2, r3);
}

// -------------------- fp16 2-term tensor-core GEMM --------------------
// C[M,N] = A[M,K] @ W[N,K]^T + bias; A fp16 hi-only, W dual fp16 planes (K-major).
// D = a * (wh + wl): 2 mma per (mt,nt) k-step. Block 128x128, BK=32, 8 warps.
// EPI: 1 = bias+GELU -> fp16 ; 2 = bias+residual -> fp32 ;
//      3 = QKV: Q->hi plane, K->dual planes, V->transposed dual planes
#define GPITCH 40
#define A_ELE (128 * GPITCH)
#define W_ELE (128 * GPITCH)
#define STG_ELE (A_ELE + 2 * W_ELE)           // 15360 halfs
#define GEMM_SMEM (2 * STG_ELE * 2)           // 61440 bytes

template <int EPI>
__global__ void __launch_bounds__(256, 2) gemm_f16(
    const __half* __restrict__ A,
    const __half* __restrict__ Wh, const __half* __restrict__ Wl,
    const float* __restrict__ bias, const float* __restrict__ res,
    float* __restrict__ Cf, __half* __restrict__ Ch, __half* __restrict__ Kl,
    __half* __restrict__ Vth, __half* __restrict__ Vtl,
    int M, int N, int K)
{
    extern __shared__ __half smem[];
    uint32_t sbase = smem_u32(smem);

    int tid  = threadIdx.x;
    int lane = tid & 31;
    int wid  = tid >> 5;
    int warpM = (wid >> 1) * 32;
    int warpN = (wid & 1) * 64;
    int m0 = blockIdx.y * 128;
    int n0 = blockIdx.x * 128;

    int gr = lane >> 2;
    int gc = lane & 3;

    float acc[2][8][4];
    #pragma unroll
    for (int i = 0; i < 2; i++)
        #pragma unroll
        for (int j = 0; j < 8; j++)
            #pragma unroll
            for (int c = 0; c < 4; c++) acc[i][j][c] = 0.f;

    int KT = K >> 5;

    auto load_chunk = [&](int kt) {
        uint32_t sb = sbase + (uint32_t)(kt & 1) * STG_ELE * 2;
        int k0 = kt << 5;
        #pragma unroll
        for (int i = 0; i < 2; i++) {
            int idx = tid + i * 256;
            int row = idx >> 2;
            int k16 = idx & 3;
            uint32_t so = (uint32_t)(row * 80 + k16 * 16);
            size_t ga = (size_t)(m0 + row) * K + k0 + k16 * 8;
            size_t gw = (size_t)(n0 + row) * K + k0 + k16 * 8;
            cp_async16(sb + so, A + ga);
            cp_async16(sb + A_ELE * 2 + so, Wh + gw);
            cp_async16(sb + (A_ELE + W_ELE) * 2 + so, Wl + gw);
        }
        cp_commit();
    };

    load_chunk(0);

    for (int kt = 0; kt < KT; kt++) {
        cp_wait0();
        __syncthreads();
        if (kt + 1 < KT) load_chunk(kt + 1);

        const char* stg = (const char*)smem + (size_t)(kt & 1) * STG_ELE * 2;
        const char* sA  = stg;
        const char* sWh = stg + A_ELE * 2;
        const char* sWl = stg + (A_ELE + W_ELE) * 2;

        #pragma unroll
        for (int ks = 0; ks < 2; ks++) {
            int kby = ks * 32 + gc * 4;
            uint32_t ah[2][4];
            #pragma unroll
            for (int mt = 0; mt < 2; mt++) {
                int r = warpM + mt * 16 + gr;
                const char* p0 = sA + r * 80 + kby;
                const char* p1 = sA + (r + 8) * 80 + kby;
                ah[mt][0] = *(const uint32_t*)p0;
                ah[mt][1] = *(const uint32_t*)p1;
                ah[mt][2] = *(const uint32_t*)(p0 + 16);
                ah[mt][3] = *(const uint32_t*)(p1 + 16);
            }
            #pragma unroll
            for (int np = 0; np < 4; np++) {
                int c0 = warpN + (2 * np) * 8 + gr;
                int c1 = warpN + (2 * np + 1) * 8 + gr;
                uint32_t b0h0, b0h1, b0l0, b0l1, b1h0, b1h1, b1l0, b1l1;
                {
                    const char* p = sWh + c0 * 80 + kby;
                    b0h0 = *(const uint32_t*)p; b0h1 = *(const uint32_t*)(p + 16);
                    const char* q = sWl + c0 * 80 + kby;
                    b0l0 = *(const uint32_t*)q; b0l1 = *(const uint32_t*)(q + 16);
                    const char* p2 = sWh + c1 * 80 + kby;
                    b1h0 = *(const uint32_t*)p2; b1h1 = *(const uint32_t*)(p2 + 16);
                    const char* q2 = sWl + c1 * 80 + kby;
                    b1l0 = *(const uint32_t*)q2; b1l1 = *(const uint32_t*)(q2 + 16);
                }
                float* a00 = acc[0][2 * np];
                float* a10 = acc[1][2 * np];
                float* a01 = acc[0][2 * np + 1];
                float* a11 = acc[1][2 * np + 1];
                mma_f16(a00, ah[0], b0h0, b0h1);
                mma_f16(a10, ah[1], b0h0, b0h1);
                mma_f16(a01, ah[0], b1h0, b1h1);
                mma_f16(a11, ah[1], b1h0, b1h1);
                mma_f16(a00, ah[0], b0l0, b0l1);
                mma_f16(a10, ah[1], b0l0, b0l1);
                mma_f16(a01, ah[0], b1l0, b1l1);
                mma_f16(a11, ah[1], b1l0, b1l1);
            }
        }
        __syncthreads();
    }

    // ---- epilogue ----
    #pragma unroll
    for (int mt = 0; mt < 2; mt++) {
        int r0 = m0 + warpM + mt * 16 + gr;
        #pragma unroll
        for (int nt = 0; nt < 8; nt++) {
            int col = n0 + warpN + nt * 8 + 2 * gc;
            float b0 = bias[col], b1 = bias[col + 1];
            #pragma unroll
            for (int half_ = 0; half_ < 2; half_++) {
                int row = r0 + half_ * 8;
                float v0 = acc[mt][nt][2 * half_ + 0] + b0;
                float v1 = acc[mt][nt][2 * half_ + 1] + b1;
                if (EPI == 1) {
                    v0 = 0.5f * v0 * (1.0f + erff(v0 * 0.70710678118654752f));
                    v1 = 0.5f * v1 * (1.0f + erff(v1 * 0.70710678118654752f));
                    *(uint32_t*)(Ch + (size_t)row * N + col) = packh(v0, v1);
                } else if (EPI == 2) {
                    const float2 rv = *(const float2*)(res + (size_t)row * N + col);
                    v0 += rv.x; v1 += rv.y;
                    float2 o2; o2.x = v0; o2.y = v1;
                    *(float2*)(Cf + (size_t)row * N + col) = o2;
                } else {   // EPI == 3: QKV epilogue
                    if (col >= 2 * DMODEL) {
                        // V: transposed dual planes
                        int c  = col - 2 * DMODEL;
                        int hh = c >> 6, d = c & 63;
                        int bb = row >> 11, t = row & (TSEQ - 1);
                        size_t vi = ((size_t)((bb * NHEAD + hh) * HEADDIM + d)) * TSEQ + t;
                        __half h0, l0v, h1, l1v;
                        split2h(v0, h0, l0v); split2h(v1, h1, l1v);
                        Vth[vi] = h0;        Vtl[vi] = l0v;
                        Vth[vi + TSEQ] = h1; Vtl[vi + TSEQ] = l1v;
                    } else if (col >= DMODEL) {
                        // K: dual planes
                        uint32_t ph, pl;
                        splitpackh(v0, v1, ph, pl);
                        size_t base = (size_t)row * QKPITCH + col;
                        *(uint32_t*)(Ch + base) = ph;
                        *(uint32_t*)(Kl + base) = pl;
                    } else {
                        // Q: hi only
                        *(uint32_t*)(Ch + (size_t)row * QKPITCH + col) = packh(v0, v1);
                    }
                }
            }
        }
    }
}

// -------------------- mma flash attention (fp16 2-term, causal + ALiBi) --------------------
// Grid (T/64, H, B), 128 threads = 4 warps, each warp 16 query rows.
// S = q_h·(k_h + k_l), O = p_h·(v_h + v_l).
#define KV_PITCH_B 144
#define KV_TILE_B (64 * KV_PITCH_B)
#define ATT_STAGE (4 * KV_TILE_B)
#define ATT_SMEM  (2 * ATT_STAGE)              // 73728

__global__ void __launch_bounds__(128) attn_mma_kernel(
    const __half* __restrict__ qkh, const __half* __restrict__ qkl,
    const __half* __restrict__ vth, const __half* __restrict__ vtl,
    __half* __restrict__ oh)
{
    extern __shared__ char asmem[];
    uint32_t sbase = smem_u32(asmem);

    int b = blockIdx.z, h = blockIdx.y;
    int qt = gridDim.x - 1 - blockIdx.x;       // big tiles first
    int tid = threadIdx.x, lane = tid & 31, w = tid >> 5;
    int gr = lane >> 2, gc = lane & 3;

    int hcol = h * HEADDIM;
    int qrow0 = b * TSEQ + qt * 64;

    // Q fragments: hi only
    uint32_t qh[4][4];
    {
        const __half* qp = qkh + (size_t)(qrow0 + w * 16) * QKPITCH + hcol;
        #pragma unroll
        for (int kc = 0; kc < 4; kc++) {
            int c = kc * 16 + 2 * gc;
            qh[kc][0] = *(const uint32_t*)(qp + (size_t)gr * QKPITCH + c);
            qh[kc][1] = *(const uint32_t*)(qp + (size_t)(gr + 8) * QKPITCH + c);
            qh[kc][2] = *(const uint32_t*)(qp + (size_t)gr * QKPITCH + c + 8);
            qh[kc][3] = *(const uint32_t*)(qp + (size_t)(gr + 8) * QKPITCH + c + 8);
        }
    }

    auto load_kv = [&](int kt, int s) {
        uint32_t sb = sbase + (uint32_t)s * ATT_STAGE;
        const __half* Kh = qkh + (size_t)(b * TSEQ + kt * 64) * QKPITCH + DMODEL + hcol;
        const __half* Kl = qkl + (size_t)(b * TSEQ + kt * 64) * QKPITCH + DMODEL + hcol;
        size_t vbase = (size_t)((b * NHEAD + h) * HEADDIM) * TSEQ + kt * 64;
        #pragma unroll
        for (int i = 0; i < 4; i++) {
            int idx = tid + i * 128;
            int r   = idx >> 3;
            int c16 = idx & 7;
            uint32_t so = (uint32_t)(r * KV_PITCH_B + c16 * 16);
            cp_async16(sb + so,                  Kh  + (size_t)r * QKPITCH + c16 * 8);
            cp_async16(sb + KV_TILE_B + so,      Kl  + (size_t)r * QKPITCH + c16 * 8);
            cp_async16(sb + 2 * KV_TILE_B + so,  vth + vbase + (size_t)r * TSEQ + c16 * 8);
            cp_async16(sb + 3 * KV_TILE_B + so,  vtl + vbase + (size_t)r * TSEQ + c16 * 8);
        }
        cp_commit();
    };

    float m0 = -INFINITY, m1 = -INFINITY, l0 = 0.f, l1 = 0.f;
    float acc_o[8][4];
    #pragma unroll
    for (int nt = 0; nt < 8; nt++)
        #pragma unroll
        for (int j = 0; j < 4; j++) acc_o[nt][j] = 0.f;

    float slope = exp2f(-0.5f * (float)(h + 1));
    int qpos0 = qt * 64 + w * 16 + gr;

    load_kv(0, 0);

    for (int kt = 0; kt <= qt; kt++) {
        int s = kt & 1;
        cp_wait0();
        __syncthreads();
        if (kt < qt) load_kv(kt + 1, s ^ 1);

        const char* Ksh = asmem + (size_t)s * ATT_STAGE;
        const char* Ksl = Ksh + KV_TILE_B;
        const char* Vsh = Ksh + 2 * KV_TILE_B;
        const char* Vsl = Ksh + 3 * KV_TILE_B;

        // ---- S = Q_h (K_h + K_l) ----
        float sacc[8][4];
        #pragma unroll
        for (int nt = 0; nt < 8; nt++)
            #pragma unroll
            for (int j = 0; j < 4; j++) sacc[nt][j] = 0.f;

        #pragma unroll
        for (int kc = 0; kc < 4; kc++) {
            int kby = kc * 32 + gc * 4;
            #pragma unroll
            for (int np = 0; np < 4; np++) {
                int c0 = (2 * np) * 8 + gr;
                int c1 = (2 * np + 1) * 8 + gr;
                uint32_t b0h0, b0h1, b0l0, b0l1, b1h0, b1h1, b1l0, b1l1;
                {
                    const char* p = Ksh + c0 * KV_PITCH_B + kby;
                    b0h0 = *(const uint32_t*)p; b0h1 = *(const uint32_t*)(p + 16);
                    const char* q = Ksl + c0 * KV_PITCH_B + kby;
                    b0l0 = *(const uint32_t*)q; b0l1 = *(const uint32_t*)(q + 16);
                    const char* p2 = Ksh + c1 * KV_PITCH_B + kby;
                    b1h0 = *(const uint32_t*)p2; b1h1 = *(const uint32_t*)(p2 + 16);
                    const char* q2 = Ksl + c1 * KV_PITCH_B + kby;
                    b1l0 = *(const uint32_t*)q2; b1l1 = *(const uint32_t*)(q2 + 16);
                }
                float* s0 = sacc[2 * np];
                float* s1 = sacc[2 * np + 1];
                mma_f16(s0, qh[kc], b0h0, b0h1);
                mma_f16(s1, qh[kc], b1h0, b1h1);
                mma_f16(s0, qh[kc], b0l0, b0l1);
                mma_f16(s1, qh[kc], b1l0, b1l1);
            }
        }

        // ---- mask + ALiBi + online softmax ----
        int kbase = kt * 64;
        float tmax0 = -INFINITY, tmax1 = -INFINITY;
        #pragma unroll
        for (int nt = 0; nt < 8; nt++) {
            #pragma unroll
            for (int j = 0; j < 4; j++) {
                int kp = kbase + nt * 8 + 2 * gc + (j & 1);
                int qp = qpos0 + ((j >> 1) << 3);
                float sv = (kp <= qp)
                    ? sacc[nt][j] * 0.125f + slope * (float)(kp - qp)
                    : -INFINITY;
                sacc[nt][j] = sv;
                if (j < 2) tmax0 = fmaxf(tmax0, sv);
                else       tmax1 = fmaxf(tmax1, sv);
            }
        }
        tmax0 = fmaxf(tmax0, __shfl_xor_sync(0xffffffffu, tmax0, 1));
        tmax0 = fmaxf(tmax0, __shfl_xor_sync(0xffffffffu, tmax0, 2));
        tmax1 = fmaxf(tmax1, __shfl_xor_sync(0xffffffffu, tmax1, 1));
        tmax1 = fmaxf(tmax1, __shfl_xor_sync(0xffffffffu, tmax1, 2));

        float nm0 = fmaxf(m0, tmax0);
        float nm1 = fmaxf(m1, tmax1);
        float corr0 = __expf(m0 - nm0);
        float corr1 = __expf(m1 - nm1);
        m0 = nm0; m1 = nm1;
        l0 *= corr0; l1 *= corr1;
        #pragma unroll
        for (int nt = 0; nt < 8; nt++) {
            acc_o[nt][0] *= corr0; acc_o[nt][1] *= corr0;
            acc_o[nt][2] *= corr1; acc_o[nt][3] *= corr1;
        }

        float ts0 = 0.f, ts1 = 0.f;
        #pragma unroll
        for (int nt = 0; nt < 8; nt++) {
            #pragma unroll
            for (int j = 0; j < 4; j++) {
                float p = __expf(sacc[nt][j] - ((j < 2) ? m0 : m1));
                sacc[nt][j] = p;
                if (j < 2) ts0 += p; else ts1 += p;
            }
        }
        ts0 += __shfl_xor_sync(0xffffffffu, ts0, 1);
        ts0 += __shfl_xor_sync(0xffffffffu, ts0, 2);
        ts1 += __shfl_xor_sync(0xffffffffu, ts1, 1);
        ts1 += __shfl_xor_sync(0xffffffffu, ts1, 2);
        l0 += ts0; l1 += ts1;

        // ---- O += P_h (V_h + V_l) ----
        #pragma unroll
        for (int kc = 0; kc < 4; kc++) {
            uint32_t ph[4];
            ph[0] = packh(sacc[2 * kc][0],     sacc[2 * kc][1]);
            ph[1] = packh(sacc[2 * kc][2],     sacc[2 * kc][3]);
            ph[2] = packh(sacc[2 * kc + 1][0], sacc[2 * kc + 1][1]);
            ph[3] = packh(sacc[2 * kc + 1][2], sacc[2 * kc + 1][3]);
            int kby = kc * 32 + gc * 4;
            #pragma unroll
            for (int np = 0; np < 4; np++) {
                int c0 = (2 * np) * 8 + gr;
                int c1 = (2 * np + 1) * 8 + gr;
                uint32_t b0h0, b0h1, b0l0, b0l1, b1h0, b1h1, b1l0, b1l1;
                {
                    const char* p = Vsh + c0 * KV_PITCH_B + kby;
                    b0h0 = *(const uint32_t*)p; b0h1 = *(const uint32_t*)(p + 16);
                    const char* q = Vsl + c0 * KV_PITCH_B + kby;
                    b0l0 = *(const uint32_t*)q; b0l1 = *(const uint32_t*)(q + 16);
                    const char* p2 = Vsh + c1 * KV_PITCH_B + kby;
                    b1h0 = *(const uint32_t*)p2; b1h1 = *(const uint32_t*)(p2 + 16);
                    const char* q2 = Vsl + c1 * KV_PITCH_B + kby;
                    b1l0 = *(const uint32_t*)q2; b1l1 = *(const uint32_t*)(q2 + 16);
                }
                float* o0 = acc_o[2 * np];
                float* o1 = acc_o[2 * np + 1];
                mma_f16(o0, ph, b0h0, b0h1);
                mma_f16(o1, ph, b1h0, b1h1);
                mma_f16(o0, ph, b0l0, b0l1);
                mma_f16(o1, ph, b1l0, b1l1);
            }
        }
    }

    // ---- epilogue: divide by l, write fp16 hi ----
    float inv0 = 1.0f / l0, inv1 = 1.0f / l1;
    int r0 = qrow0 + w * 16 + gr;
    #pragma unroll
    for (int nt = 0; nt < 8; nt++) {
        int col = hcol + nt * 8 + 2 * gc;
        size_t b0 = (size_t)r0 * DMODEL + col;
        size_t b1 = (size_t)(r0 + 8) * DMODEL + col;
        *(uint32_t*)(oh + b0) = packh(acc_o[nt][0] * inv0, acc_o[nt][1] * inv0);
        *(uint32_t*)(oh + b1) = packh(acc_o[nt][2] * inv1, acc_o[nt][3] * inv1);
    }
}

// -------------------- launch --------------------
extern "C" void kernel_launch(void* const* d_in, const int* in_sizes, int n_in,
                              void* d_out, int out_size)
{
    const float* x        = (const float*)d_in[0];
    const float* in_w     = (const float*)d_in[1];
    const float* in_b     = (const float*)d_in[2];
    const float* out_w    = (const float*)d_in[3];
    const float* out_b    = (const float*)d_in[4];
    const float* f1_w     = (const float*)d_in[5];
    const float* f1_b     = (const float*)d_in[6];
    const float* f2_w     = (const float*)d_in[7];
    const float* f2_b     = (const float*)d_in[8];
    const float* ln1_w    = (const float*)d_in[9];
    const float* ln1_b    = (const float*)d_in[10];
    const float* ln2_w    = (const float*)d_in[11];
    const float* ln2_b    = (const float*)d_in[12];
    const float* final_w  = (const float*)d_in[13];
    const float* final_b  = (const float*)d_in[14];

    float *x_;
    __half *xn, *att, *hbuf, *qkh, *qkl, *vth, *vtl;
    __half *wih, *wil, *woh, *wol, *w1h, *w1l, *w2h, *w2l;
    cudaGetSymbolAddress((void**)&x_,   g_x);
    cudaGetSymbolAddress((void**)&xn,   g_xn);
    cudaGetSymbolAddress((void**)&att,  g_att);
    cudaGetSymbolAddress((void**)&hbuf, g_h);
    cudaGetSymbolAddress((void**)&qkh,  g_qk_h);
    cudaGetSymbolAddress((void**)&qkl,  g_qk_l);
    cudaGetSymbolAddress((void**)&vth,  g_vt_h);
    cudaGetSymbolAddress((void**)&vtl,  g_vt_l);
    cudaGetSymbolAddress((void**)&wih,  g_wi_h);
    cudaGetSymbolAddress((void**)&wil,  g_wi_l);
    cudaGetSymbolAddress((void**)&woh,  g_wo_h);
    cudaGetSymbolAddress((void**)&wol,  g_wo_l);
    cudaGetSymbolAddress((void**)&w1h,  g_w1_h);
    cudaGetSymbolAddress((void**)&w1l,  g_w1_l);
    cudaGetSymbolAddress((void**)&w2h,  g_w2_h);
    cudaGetSymbolAddress((void**)&w2l,  g_w2_l);

    cudaFuncSetAttribute(gemm_f16<1>, cudaFuncAttributeMaxDynamicSharedMemorySize, GEMM_SMEM);
    cudaFuncSetAttribute(gemm_f16<2>, cudaFuncAttributeMaxDynamicSharedMemorySize, GEMM_SMEM);
    cudaFuncSetAttribute(gemm_f16<3>, cudaFuncAttributeMaxDynamicSharedMemorySize, GEMM_SMEM);
    cudaFuncSetAttribute(attn_mma_kernel, cudaFuncAttributeMaxDynamicSharedMemorySize, ATT_SMEM);

    split_all_kernel<<<(SPLIT_TOTAL + 255) / 256, 256>>>(
        (const float4*)in_w, (const float4*)out_w, (const float4*)f1_w, (const float4*)f2_w,
        (uint32_t*)wih, (uint32_t*)wil,
        (uint32_t*)woh, (uint32_t*)wol,
        (uint32_t*)w1h, (uint32_t*)w1l,
        (uint32_t*)w2h, (uint32_t*)w2l);

    {
        int n4 = ROWS * DMODEL / 4;
        copy_kernel<<<(n4 + 255) / 256, 256>>>((const float4*)x, (float4*)x_, n4);
    }

    dim3 blk256(256);
    for (int i = 0; i < NLAYER; i++) {
        __half* iwh = wih + (size_t)i * QKVDIM * DMODEL;
        __half* iwl = wil + (size_t)i * QKVDIM * DMODEL;
        __half* owh = woh + (size_t)i * DMODEL * DMODEL;
        __half* owl = wol + (size_t)i * DMODEL * DMODEL;
        __half* f1h = w1h + (size_t)i * FFDIM * DMODEL;
        __half* f1l = w1l + (size_t)i * FFDIM * DMODEL;
        __half* f2h = w2h + (size_t)i * DMODEL * FFDIM;
        __half* f2l = w2l + (size_t)i * DMODEL * FFDIM;
        const float* ib = in_b  + (size_t)i * QKVDIM;
        const float* ob = out_b + (size_t)i * DMODEL;
        const float* b1 = f1_b  + (size_t)i * FFDIM;
        const float* b2 = f2_b  + (size_t)i * DMODEL;

        ln_half_kernel<<<ROWS, blk256>>>(x_, ln1_w + i * DMODEL, ln1_b + i * DMODEL, xn);
        gemm_f16<3><<<dim3(QKVDIM / 128, ROWS / 128), blk256, GEMM_SMEM>>>(
            xn, iwh, iwl, ib, nullptr, nullptr, qkh, qkl, vth, vtl,
            ROWS, QKVDIM, DMODEL);
        attn_mma_kernel<<<dim3(TSEQ / 64, NHEAD, BATCH), 128, ATT_SMEM>>>(
            qkh, qkl, vth, vtl, att);
        gemm_f16<2><<<dim3(DMODEL / 128, ROWS / 128), blk256, GEMM_SMEM>>>(
            att, owh, owl, ob, x_, x_, nullptr, nullptr, nullptr, nullptr,
            ROWS, DMODEL, DMODEL);
        ln_half_kernel<<<ROWS, blk256>>>(x_, ln2_w + i * DMODEL, ln2_b + i * DMODEL, xn);
        gemm_f16<1><<<dim3(FFDIM / 128, ROWS / 128), blk256, GEMM_SMEM>>>(
            xn, f1h, f1l, b1, nullptr, nullptr, hbuf, nullptr, nullptr, nullptr,
            ROWS, FFDIM, DMODEL);
        gemm_f16<2><<<dim3(DMODEL / 128, ROWS / 128), blk256, GEMM_SMEM>>>(
            hbuf, f2h, f2l, b2, x_, x_, nullptr, nullptr, nullptr, nullptr,
            ROWS, DMODEL, FFDIM);
    }
    ln_kernel<<<ROWS, blk256>>>(x_, final_w, final_b, (float*)d_out);
}

// round 16
// speedup vs baseline: 2.1017x; 1.4049x over previous
#include <cuda_runtime.h>
#include <cuda_fp16.h>
#include <math.h>
#include <stdint.h>

// Problem constants
#define TSEQ    2048
#define BATCH   2
#define DMODEL  1024
#define NHEAD   16
#define HEADDIM 64
#define FFDIM   4096
#define NLAYER  4
#define ROWS    (BATCH * TSEQ)          // 4096
#define QKVDIM  (3 * DMODEL)            // 3072
#define QKPITCH (2 * DMODEL)            // 2048

// -------------------- scratch (allocation-free) --------------------
__device__ float g_x  [ROWS * DMODEL];          // residual stream fp32
__device__ __half g_xn [ROWS * DMODEL];
__device__ __half g_att[ROWS * DMODEL];
__device__ __half g_h  [ROWS * FFDIM];
// Q(hi)+K(hi) packed plane, K(lo) plane, V transposed dual planes
__device__ __half g_qk_h[ROWS * QKPITCH];
__device__ __half g_qk_l[ROWS * QKPITCH];
__device__ __half g_vt_h[BATCH * NHEAD * HEADDIM * TSEQ];
__device__ __half g_vt_l[BATCH * NHEAD * HEADDIM * TSEQ];
// single fp16 weight planes
__device__ __half g_wi[NLAYER * QKVDIM * DMODEL];
__device__ __half g_wo[NLAYER * DMODEL * DMODEL];
__device__ __half g_w1[NLAYER * FFDIM * DMODEL];
__device__ __half g_w2[NLAYER * DMODEL * FFDIM];

// -------------------- helpers --------------------
__device__ __forceinline__ void cp_async16(uint32_t smem, const void* g) {
    asm volatile("cp.async.cg.shared.global [%0], [%1], 16;\n" :: "r"(smem), "l"(g));
}
__device__ __forceinline__ void cp_commit() {
    asm volatile("cp.async.commit_group;\n" ::: "memory");
}
__device__ __forceinline__ void cp_wait0() {
    asm volatile("cp.async.wait_group 0;\n" ::: "memory");
}
__device__ __forceinline__ uint32_t smem_u32(const void* p) {
    return (uint32_t)__cvta_generic_to_shared(p);
}
__device__ __forceinline__ void split2h(float v, __half& h, __half& l) {
    h = __float2half_rn(v);
    l = __float2half_rn(v - __half2float(h));
}
__device__ __forceinline__ uint32_t packh(float a, float b) {
    __half2 t = __floats2half2_rn(a, b);
    return *(uint32_t*)&t;
}
__device__ __forceinline__ void splitpackh(float a, float b, uint32_t& hi, uint32_t& lo) {
    __half ha, la, hb, lb;
    split2h(a, ha, la); split2h(b, hb, lb);
    __half2 ph; ph.x = ha; ph.y = hb;
    __half2 pl; pl.x = la; pl.y = lb;
    hi = *(uint32_t*)&ph; lo = *(uint32_t*)&pl;
}
__device__ __forceinline__ void mma_f16(float* d, const uint32_t* a, uint32_t b0, uint32_t b1) {
    asm volatile(
        "mma.sync.aligned.m16n8k16.row.col.f32.f16.f16.f32 "
        "{%0,%1,%2,%3}, {%4,%5,%6,%7}, {%8,%9}, {%0,%1,%2,%3};\n"
        : "+f"(d[0]), "+f"(d[1]), "+f"(d[2]), "+f"(d[3])
        : "r"(a[0]), "r"(a[1]), "r"(a[2]), "r"(a[3]),
          "r"(b0), "r"(b1));
}

// -------------------- copy --------------------
__global__ void copy_kernel(const float4* __restrict__ in, float4* __restrict__ out, int n4) {
    int i = blockIdx.x * blockDim.x + threadIdx.x;
    if (i < n4) out[i] = in[i];
}

// -------------------- merged weight convert (fp32 -> fp16 single plane) --------------------
#define S0 (NLAYER * QKVDIM * DMODEL / 4)
#define S1 (NLAYER * DMODEL * DMODEL / 4)
#define S2 (NLAYER * FFDIM * DMODEL / 4)
#define S3 (NLAYER * DMODEL * FFDIM / 4)
#define SPLIT_TOTAL (S0 + S1 + S2 + S3)

__global__ void convert_all_kernel(
    const float4* __restrict__ in0, const float4* __restrict__ in1,
    const float4* __restrict__ in2, const float4* __restrict__ in3,
    uint32_t* __restrict__ h0, uint32_t* __restrict__ h1,
    uint32_t* __restrict__ h2, uint32_t* __restrict__ h3)
{
    int i = blockIdx.x * blockDim.x + threadIdx.x;
    if (i >= SPLIT_TOTAL) return;
    const float4* in; uint32_t* hi;
    int j = i;
    if (j < S0)                 { in = in0; hi = h0; }
    else if ((j -= S0) < S1)    { in = in1; hi = h1; }
    else if ((j -= S1) < S2)    { in = in2; hi = h2; }
    else                        { j -= S2; in = in3; hi = h3; }
    float4 v = in[j];
    hi[j * 2 + 0] = packh(v.x, v.y);
    hi[j * 2 + 1] = packh(v.z, v.w);
}

// -------------------- layernorm (fp32 out — final) --------------------
__global__ void __launch_bounds__(256) ln_kernel(
    const float* __restrict__ in, const float* __restrict__ w,
    const float* __restrict__ b, float* __restrict__ out)
{
    int row = blockIdx.x;
    int tid = threadIdx.x;
    const float4* ip = (const float4*)(in + (size_t)row * DMODEL);
    float4 v = ip[tid];
    float s  = v.x + v.y + v.z + v.w;
    float sq = v.x * v.x + v.y * v.y + v.z * v.z + v.w * v.w;
    #pragma unroll
    for (int o = 16; o > 0; o >>= 1) {
        s  += __shfl_xor_sync(0xffffffffu, s,  o);
        sq += __shfl_xor_sync(0xffffffffu, sq, o);
    }
    __shared__ float reds[8], redq[8];
    int lane = tid & 31, wid = tid >> 5;
    if (lane == 0) { reds[wid] = s; redq[wid] = sq; }
    __syncthreads();
    float ts = 0.f, tq = 0.f;
    #pragma unroll
    for (int i = 0; i < 8; i++) { ts += reds[i]; tq += redq[i]; }
    float mean = ts * (1.0f / DMODEL);
    float var  = tq * (1.0f / DMODEL) - mean * mean;
    float rstd = rsqrtf(var + 1e-5f);
    float4 wv = ((const float4*)w)[tid];
    float4 bv = ((const float4*)b)[tid];
    float4 r;
    r.x = (v.x - mean) * rstd * wv.x + bv.x;
    r.y = (v.y - mean) * rstd * wv.y + bv.y;
    r.z = (v.z - mean) * rstd * wv.z + bv.z;
    r.w = (v.w - mean) * rstd * wv.w + bv.w;
    ((float4*)(out + (size_t)row * DMODEL))[tid] = r;
}

// -------------------- layernorm (fp16 out) --------------------
__global__ void __launch_bounds__(256) ln_half_kernel(
    const float* __restrict__ in, const float* __restrict__ w,
    const float* __restrict__ b, __half* __restrict__ oh)
{
    int row = blockIdx.x;
    int tid = threadIdx.x;
    const float4* ip = (const float4*)(in + (size_t)row * DMODEL);
    float4 v = ip[tid];
    float s  = v.x + v.y + v.z + v.w;
    float sq = v.x * v.x + v.y * v.y + v.z * v.z + v.w * v.w;
    #pragma unroll
    for (int o = 16; o > 0; o >>= 1) {
        s  += __shfl_xor_sync(0xffffffffu, s,  o);
        sq += __shfl_xor_sync(0xffffffffu, sq, o);
    }
    __shared__ float reds[8], redq[8];
    int lane = tid & 31, wid = tid >> 5;
    if (lane == 0) { reds[wid] = s; redq[wid] = sq; }
    __syncthreads();
    float ts = 0.f, tq = 0.f;
    #pragma unroll
    for (int i = 0; i < 8; i++) { ts += reds[i]; tq += redq[i]; }
    float mean = ts * (1.0f / DMODEL);
    float var  = tq * (1.0f / DMODEL) - mean * mean;
    float rstd = rsqrtf(var + 1e-5f);
    float4 wv = ((const float4*)w)[tid];
    float4 bv = ((const float4*)b)[tid];
    float r0 = (v.x - mean) * rstd * wv.x + bv.x;
    float r1 = (v.y - mean) * rstd * wv.y + bv.y;
    float r2 = (v.z - mean) * rstd * wv.z + bv.z;
    float r3 = (v.w - mean) * rstd * wv.w + bv.w;
    size_t base = (size_t)row * DMODEL + tid * 4;
    *(uint32_t*)(oh + base)     = packh(r0, r1);
    *(uint32_t*)(oh + base + 2) = packh(r2, r3);
}

// -------------------- pure-fp16 tensor-core GEMM --------------------
// C[M,N] = A[M,K] @ W[N,K]^T + bias; A,W fp16 single planes (K-major).
// 1 mma per (mt,nt) k-step. Block 128x128, BK=32, 8 warps (4M x 2N), warp 32x64.
// EPI: 1 = bias+GELU -> fp16 ; 2 = bias+residual -> fp32 ;
//      3 = QKV: Q->hi plane, K->dual planes, V->transposed dual planes
#define GPITCH 40
#define A_ELE (128 * GPITCH)
#define W_ELE (128 * GPITCH)
#define STG_ELE (A_ELE + W_ELE)               // 10240 halfs
#define GEMM_SMEM (2 * STG_ELE * 2)           // 40960 bytes

template <int EPI>
__global__ void __launch_bounds__(256, 2) gemm_f16(
    const __half* __restrict__ A, const __half* __restrict__ W,
    const float* __restrict__ bias, const float* __restrict__ res,
    float* __restrict__ Cf, __half* __restrict__ Ch, __half* __restrict__ Kl,
    __half* __restrict__ Vth, __half* __restrict__ Vtl,
    int M, int N, int K)
{
    extern __shared__ __half smem[];
    uint32_t sbase = smem_u32(smem);

    int tid  = threadIdx.x;
    int lane = tid & 31;
    int wid  = tid >> 5;
    int warpM = (wid >> 1) * 32;
    int warpN = (wid & 1) * 64;
    int m0 = blockIdx.y * 128;
    int n0 = blockIdx.x * 128;

    int gr = lane >> 2;
    int gc = lane & 3;

    float acc[2][8][4];
    #pragma unroll
    for (int i = 0; i < 2; i++)
        #pragma unroll
        for (int j = 0; j < 8; j++)
            #pragma unroll
            for (int c = 0; c < 4; c++) acc[i][j][c] = 0.f;

    int KT = K >> 5;

    auto load_chunk = [&](int kt) {
        uint32_t sb = sbase + (uint32_t)(kt & 1) * STG_ELE * 2;
        int k0 = kt << 5;
        #pragma unroll
        for (int i = 0; i < 2; i++) {
            int idx = tid + i * 256;
            int row = idx >> 2;
            int k16 = idx & 3;
            uint32_t so = (uint32_t)(row * 80 + k16 * 16);
            size_t ga = (size_t)(m0 + row) * K + k0 + k16 * 8;
            size_t gw = (size_t)(n0 + row) * K + k0 + k16 * 8;
            cp_async16(sb + so, A + ga);
            cp_async16(sb + A_ELE * 2 + so, W + gw);
        }
        cp_commit();
    };

    load_chunk(0);

    for (int kt = 0; kt < KT; kt++) {
        cp_wait0();
        __syncthreads();
        if (kt + 1 < KT) load_chunk(kt + 1);

        const char* stg = (const char*)smem + (size_t)(kt & 1) * STG_ELE * 2;
        const char* sA = stg;
        const char* sW = stg + A_ELE * 2;

        #pragma unroll
        for (int ks = 0; ks < 2; ks++) {
            int kby = ks * 32 + gc * 4;
            uint32_t ah[2][4];
            #pragma unroll
            for (int mt = 0; mt < 2; mt++) {
                int r = warpM + mt * 16 + gr;
                const char* p0 = sA + r * 80 + kby;
                const char* p1 = sA + (r + 8) * 80 + kby;
                ah[mt][0] = *(const uint32_t*)p0;
                ah[mt][1] = *(const uint32_t*)p1;
                ah[mt][2] = *(const uint32_t*)(p0 + 16);
                ah[mt][3] = *(const uint32_t*)(p1 + 16);
            }
            #pragma unroll
            for (int np = 0; np < 4; np++) {
                int c0 = warpN + (2 * np) * 8 + gr;
                int c1 = warpN + (2 * np + 1) * 8 + gr;
                uint32_t b00, b01, b10, b11;
                {
                    const char* p = sW + c0 * 80 + kby;
                    b00 = *(const uint32_t*)p; b01 = *(const uint32_t*)(p + 16);
                    const char* p2 = sW + c1 * 80 + kby;
                    b10 = *(const uint32_t*)p2; b11 = *(const uint32_t*)(p2 + 16);
                }
                mma_f16(acc[0][2 * np],     ah[0], b00, b01);
                mma_f16(acc[1][2 * np],     ah[1], b00, b01);
                mma_f16(acc[0][2 * np + 1], ah[0], b10, b11);
                mma_f16(acc[1][2 * np + 1], ah[1], b10, b11);
            }
        }
        __syncthreads();
    }

    // ---- epilogue ----
    #pragma unroll
    for (int mt = 0; mt < 2; mt++) {
        int r0 = m0 + warpM + mt * 16 + gr;
        #pragma unroll
        for (int nt = 0; nt < 8; nt++) {
            int col = n0 + warpN + nt * 8 + 2 * gc;
            float b0 = bias[col], b1 = bias[col + 1];
            #pragma unroll
            for (int half_ = 0; half_ < 2; half_++) {
                int row = r0 + half_ * 8;
                float v0 = acc[mt][nt][2 * half_ + 0] + b0;
                float v1 = acc[mt][nt][2 * half_ + 1] + b1;
                if (EPI == 1) {
                    v0 = 0.5f * v0 * (1.0f + erff(v0 * 0.70710678118654752f));
                    v1 = 0.5f * v1 * (1.0f + erff(v1 * 0.70710678118654752f));
                    *(uint32_t*)(Ch + (size_t)row * N + col) = packh(v0, v1);
                } else if (EPI == 2) {
                    const float2 rv = *(const float2*)(res + (size_t)row * N + col);
                    v0 += rv.x; v1 += rv.y;
                    float2 o2; o2.x = v0; o2.y = v1;
                    *(float2*)(Cf + (size_t)row * N + col) = o2;
                } else {   // EPI == 3: QKV epilogue
                    if (col >= 2 * DMODEL) {
                        int c  = col - 2 * DMODEL;
                        int hh = c >> 6, d = c & 63;
                        int bb = row >> 11, t = row & (TSEQ - 1);
                        size_t vi = ((size_t)((bb * NHEAD + hh) * HEADDIM + d)) * TSEQ + t;
                        __half h0, l0v, h1, l1v;
                        split2h(v0, h0, l0v); split2h(v1, h1, l1v);
                        Vth[vi] = h0;        Vtl[vi] = l0v;
                        Vth[vi + TSEQ] = h1; Vtl[vi + TSEQ] = l1v;
                    } else if (col >= DMODEL) {
                        uint32_t ph, pl;
                        splitpackh(v0, v1, ph, pl);
                        size_t base = (size_t)row * QKPITCH + col;
                        *(uint32_t*)(Ch + base) = ph;
                        *(uint32_t*)(Kl + base) = pl;
                    } else {
                        *(uint32_t*)(Ch + (size_t)row * QKPITCH + col) = packh(v0, v1);
                    }
                }
            }
        }
    }
}

// -------------------- mma flash attention (fp16 2-term, causal + ALiBi) --------------------
#define KV_PITCH_B 144
#define KV_TILE_B (64 * KV_PITCH_B)
#define ATT_STAGE (4 * KV_TILE_B)
#define ATT_SMEM  (2 * ATT_STAGE)              // 73728

__global__ void __launch_bounds__(128) attn_mma_kernel(
    const __half* __restrict__ qkh, const __half* __restrict__ qkl,
    const __half* __restrict__ vth, const __half* __restrict__ vtl,
    __half* __restrict__ oh)
{
    extern __shared__ char asmem[];
    uint32_t sbase = smem_u32(asmem);

    int b = blockIdx.z, h = blockIdx.y;
    int qt = gridDim.x - 1 - blockIdx.x;
    int tid = threadIdx.x, lane = tid & 31, w = tid >> 5;
    int gr = lane >> 2, gc = lane & 3;

    int hcol = h * HEADDIM;
    int qrow0 = b * TSEQ + qt * 64;

    uint32_t qh[4][4];
    {
        const __half* qp = qkh + (size_t)(qrow0 + w * 16) * QKPITCH + hcol;
        #pragma unroll
        for (int kc = 0; kc < 4; kc++) {
            int c = kc * 16 + 2 * gc;
            qh[kc][0] = *(const uint32_t*)(qp + (size_t)gr * QKPITCH + c);
            qh[kc][1] = *(const uint32_t*)(qp + (size_t)(gr + 8) * QKPITCH + c);
            qh[kc][2] = *(const uint32_t*)(qp + (size_t)gr * QKPITCH + c + 8);
            qh[kc][3] = *(const uint32_t*)(qp + (size_t)(gr + 8) * QKPITCH + c + 8);
        }
    }

    auto load_kv = [&](int kt, int s) {
        uint32_t sb = sbase + (uint32_t)s * ATT_STAGE;
        const __half* Kh = qkh + (size_t)(b * TSEQ + kt * 64) * QKPITCH + DMODEL + hcol;
        const __half* Kl = qkl + (size_t)(b * TSEQ + kt * 64) * QKPITCH + DMODEL + hcol;
        size_t vbase = (size_t)((b * NHEAD + h) * HEADDIM) * TSEQ + kt * 64;
        #pragma unroll
        for (int i = 0; i < 4; i++) {
            int idx = tid + i * 128;
            int r   = idx >> 3;
            int c16 = idx & 7;
            uint32_t so = (uint32_t)(r * KV_PITCH_B + c16 * 16);
            cp_async16(sb + so,                  Kh  + (size_t)r * QKPITCH + c16 * 8);
            cp_async16(sb + KV_TILE_B + so,      Kl  + (size_t)r * QKPITCH + c16 * 8);
            cp_async16(sb + 2 * KV_TILE_B + so,  vth + vbase + (size_t)r * TSEQ + c16 * 8);
            cp_async16(sb + 3 * KV_TILE_B + so,  vtl + vbase + (size_t)r * TSEQ + c16 * 8);
        }
        cp_commit();
    };

    float m0 = -INFINITY, m1 = -INFINITY, l0 = 0.f, l1 = 0.f;
    float acc_o[8][4];
    #pragma unroll
    for (int nt = 0; nt < 8; nt++)
        #pragma unroll
        for (int j = 0; j < 4; j++) acc_o[nt][j] = 0.f;

    float slope = exp2f(-0.5f * (float)(h + 1));
    int qpos0 = qt * 64 + w * 16 + gr;

    load_kv(0, 0);

    for (int kt = 0; kt <= qt; kt++) {
        int s = kt & 1;
        cp_wait0();
        __syncthreads();
        if (kt < qt) load_kv(kt + 1, s ^ 1);

        const char* Ksh = asmem + (size_t)s * ATT_STAGE;
        const char* Ksl = Ksh + KV_TILE_B;
        const char* Vsh = Ksh + 2 * KV_TILE_B;
        const char* Vsl = Ksh + 3 * KV_TILE_B;

        // ---- S = Q_h (K_h + K_l) ----
        float sacc[8][4];
        #pragma unroll
        for (int nt = 0; nt < 8; nt++)
            #pragma unroll
            for (int j = 0; j < 4; j++) sacc[nt][j] = 0.f;

        #pragma unroll
        for (int kc = 0; kc < 4; kc++) {
            int kby = kc * 32 + gc * 4;
            #pragma unroll
            for (int np = 0; np < 4; np++) {
                int c0 = (2 * np) * 8 + gr;
                int c1 = (2 * np + 1) * 8 + gr;
                uint32_t b0h0, b0h1, b0l0, b0l1, b1h0, b1h1, b1l0, b1l1;
                {
                    const char* p = Ksh + c0 * KV_PITCH_B + kby;
                    b0h0 = *(const uint32_t*)p; b0h1 = *(const uint32_t*)(p + 16);
                    const char* q = Ksl + c0 * KV_PITCH_B + kby;
                    b0l0 = *(const uint32_t*)q; b0l1 = *(const uint32_t*)(q + 16);
                    const char* p2 = Ksh + c1 * KV_PITCH_B + kby;
                    b1h0 = *(const uint32_t*)p2; b1h1 = *(const uint32_t*)(p2 + 16);
                    const char* q2 = Ksl + c1 * KV_PITCH_B + kby;
                    b1l0 = *(const uint32_t*)q2; b1l1 = *(const uint32_t*)(q2 + 16);
                }
                float* s0 = sacc[2 * np];
                float* s1 = sacc[2 * np + 1];
                mma_f16(s0, qh[kc], b0h0, b0h1);
                mma_f16(s1, qh[kc], b1h0, b1h1);
                mma_f16(s0, qh[kc], b0l0, b0l1);
                mma_f16(s1, qh[kc], b1l0, b1l1);
            }
        }

        // ---- mask + ALiBi + online softmax ----
        int kbase = kt * 64;
        float tmax0 = -INFINITY, tmax1 = -INFINITY;
        #pragma unroll
        for (int nt = 0; nt < 8; nt++) {
            #pragma unroll
            for (int j = 0; j < 4; j++) {
                int kp = kbase + nt * 8 + 2 * gc + (j & 1);
                int qp = qpos0 + ((j >> 1) << 3);
                float sv = (kp <= qp)
                    ? sacc[nt][j] * 0.125f + slope * (float)(kp - qp)
                    : -INFINITY;
                sacc[nt][j] = sv;
                if (j < 2) tmax0 = fmaxf(tmax0, sv);
                else       tmax1 = fmaxf(tmax1, sv);
            }
        }
        tmax0 = fmaxf(tmax0, __shfl_xor_sync(0xffffffffu, tmax0, 1));
        tmax0 = fmaxf(tmax0, __shfl_xor_sync(0xffffffffu, tmax0, 2));
        tmax1 = fmaxf(tmax1, __shfl_xor_sync(0xffffffffu, tmax1, 1));
        tmax1 = fmaxf(tmax1, __shfl_xor_sync(0xffffffffu, tmax1, 2));

        float nm0 = fmaxf(m0, tmax0);
        float nm1 = fmaxf(m1, tmax1);
        float corr0 = __expf(m0 - nm0);
        float corr1 = __expf(m1 - nm1);
        m0 = nm0; m1 = nm1;
        l0 *= corr0; l1 *= corr1;
        #pragma unroll
        for (int nt = 0; nt < 8; nt++) {
            acc_o[nt][0] *= corr0; acc_o[nt][1] *= corr0;
            acc_o[nt][2] *= corr1; acc_o[nt][3] *= corr1;
        }

        float ts0 = 0.f, ts1 = 0.f;
        #pragma unroll
        for (int nt = 0; nt < 8; nt++) {
            #pragma unroll
            for (int j = 0; j < 4; j++) {
                float p = __expf(sacc[nt][j] - ((j < 2) ? m0 : m1));
                sacc[nt][j] = p;
                if (j < 2) ts0 += p; else ts1 += p;
            }
        }
        ts0 += __shfl_xor_sync(0xffffffffu, ts0, 1);
        ts0 += __shfl_xor_sync(0xffffffffu, ts0, 2);
        ts1 += __shfl_xor_sync(0xffffffffu, ts1, 1);
        ts1 += __shfl_xor_sync(0xffffffffu, ts1, 2);
        l0 += ts0; l1 += ts1;

        // ---- O += P_h (V_h + V_l) ----
        #pragma unroll
        for (int kc = 0; kc < 4; kc++) {
            uint32_t ph[4];
            ph[0] = packh(sacc[2 * kc][0],     sacc[2 * kc][1]);
            ph[1] = packh(sacc[2 * kc][2],     sacc[2 * kc][3]);
            ph[2] = packh(sacc[2 * kc + 1][0], sacc[2 * kc + 1][1]);
            ph[3] = packh(sacc[2 * kc + 1][2], sacc[2 * kc + 1][3]);
            int kby = kc * 32 + gc * 4;
            #pragma unroll
            for (int np = 0; np < 4; np++) {
                int c0 = (2 * np) * 8 + gr;
                int c1 = (2 * np + 1) * 8 + gr;
                uint32_t b0h0, b0h1, b0l0, b0l1, b1h0, b1h1, b1l0, b1l1;
                {
                    const char* p = Vsh + c0 * KV_PITCH_B + kby;
                    b0h0 = *(const uint32_t*)p; b0h1 = *(const uint32_t*)(p + 16);
                    const char* q = Vsl + c0 * KV_PITCH_B + kby;
                    b0l0 = *(const uint32_t*)q; b0l1 = *(const uint32_t*)(q + 16);
                    const char* p2 = Vsh + c1 * KV_PITCH_B + kby;
                    b1h0 = *(const uint32_t*)p2; b1h1 = *(const uint32_t*)(p2 + 16);
                    const char* q2 = Vsl + c1 * KV_PITCH_B + kby;
                    b1l0 = *(const uint32_t*)q2; b1l1 = *(const uint32_t*)(q2 + 16);
                }
                float* o0 = acc_o[2 * np];
                float* o1 = acc_o[2 * np + 1];
                mma_f16(o0, ph, b0h0, b0h1);
                mma_f16(o1, ph, b1h0, b1h1);
                mma_f16(o0, ph, b0l0, b0l1);
                mma_f16(o1, ph, b1l0, b1l1);
            }
        }
    }

    // ---- epilogue ----
    float inv0 = 1.0f / l0, inv1 = 1.0f / l1;
    int r0 = qrow0 + w * 16 + gr;
    #pragma unroll
    for (int nt = 0; nt < 8; nt++) {
        int col = hcol + nt * 8 + 2 * gc;
        size_t b0 = (size_t)r0 * DMODEL + col;
        size_t b1 = (size_t)(r0 + 8) * DMODEL + col;
        *(uint32_t*)(oh + b0) = packh(acc_o[nt][0] * inv0, acc_o[nt][1] * inv0);
        *(uint32_t*)(oh + b1) = packh(acc_o[nt][2] * inv1, acc_o[nt][3] * inv1);
    }
}

// -------------------- launch --------------------
extern "C" void kernel_launch(void* const* d_in, const int* in_sizes, int n_in,
                              void* d_out, int out_size)
{
    const float* x        = (const float*)d_in[0];
    const float* in_w     = (const float*)d_in[1];
    const float* in_b     = (const float*)d_in[2];
    const float* out_w    = (const float*)d_in[3];
    const float* out_b    = (const float*)d_in[4];
    const float* f1_w     = (const float*)d_in[5];
    const float* f1_b     = (const float*)d_in[6];
    const float* f2_w     = (const float*)d_in[7];
    const float* f2_b     = (const float*)d_in[8];
    const float* ln1_w    = (const float*)d_in[9];
    const float* ln1_b    = (const float*)d_in[10];
    const float* ln2_w    = (const float*)d_in[11];
    const float* ln2_b    = (const float*)d_in[12];
    const float* final_w  = (const float*)d_in[13];
    const float* final_b  = (const float*)d_in[14];

    float *x_;
    __half *xn, *att, *hbuf, *qkh, *qkl, *vth, *vtl;
    __half *wi, *wo, *w1, *w2;
    cudaGetSymbolAddress((void**)&x_,   g_x);
    cudaGetSymbolAddress((void**)&xn,   g_xn);
    cudaGetSymbolAddress((void**)&att,  g_att);
    cudaGetSymbolAddress((void**)&hbuf, g_h);
    cudaGetSymbolAddress((void**)&qkh,  g_qk_h);
    cudaGetSymbolAddress((void**)&qkl,  g_qk_l);
    cudaGetSymbolAddress((void**)&vth,  g_vt_h);
    cudaGetSymbolAddress((void**)&vtl,  g_vt_l);
    cudaGetSymbolAddress((void**)&wi,   g_wi);
    cudaGetSymbolAddress((void**)&wo,   g_wo);
    cudaGetSymbolAddress((void**)&w1,   g_w1);
    cudaGetSymbolAddress((void**)&w2,   g_w2);

    cudaFuncSetAttribute(gemm_f16<1>, cudaFuncAttributeMaxDynamicSharedMemorySize, GEMM_SMEM);
    cudaFuncSetAttribute(gemm_f16<2>, cudaFuncAttributeMaxDynamicSharedMemorySize, GEMM_SMEM);
    cudaFuncSetAttribute(gemm_f16<3>, cudaFuncAttributeMaxDynamicSharedMemorySize, GEMM_SMEM);
    cudaFuncSetAttribute(attn_mma_kernel, cudaFuncAttributeMaxDynamicSharedMemorySize, ATT_SMEM);

    convert_all_kernel<<<(SPLIT_TOTAL + 255) / 256, 256>>>(
        (const float4*)in_w, (const float4*)out_w, (const float4*)f1_w, (const float4*)f2_w,
        (uint32_t*)wi, (uint32_t*)wo, (uint32_t*)w1, (uint32_t*)w2);

    {
        int n4 = ROWS * DMODEL / 4;
        copy_kernel<<<(n4 + 255) / 256, 256>>>((const float4*)x, (float4*)x_, n4);
    }

    dim3 blk256(256);
    for (int i = 0; i < NLAYER; i++) {
        __half* iw  = wi + (size_t)i * QKVDIM * DMODEL;
        __half* ow  = wo + (size_t)i * DMODEL * DMODEL;
        __half* f1p = w1 + (size_t)i * FFDIM * DMODEL;
        __half* f2p = w2 + (size_t)i * DMODEL * FFDIM;
        const float* ib = in_b  + (size_t)i * QKVDIM;
        const float* ob = out_b + (size_t)i * DMODEL;
        const float* b1 = f1_b  + (size_t)i * FFDIM;
        const float* b2 = f2_b  + (size_t)i * DMODEL;

        ln_half_kernel<<<ROWS, blk256>>>(x_, ln1_w + i * DMODEL, ln1_b + i * DMODEL, xn);
        gemm_f16<3><<<dim3(QKVDIM / 128, ROWS / 128), blk256, GEMM_SMEM>>>(
            xn, iw, ib, nullptr, nullptr, qkh, qkl, vth, vtl,
            ROWS, QKVDIM, DMODEL);
        attn_mma_kernel<<<dim3(TSEQ / 64, NHEAD, BATCH), 128, ATT_SMEM>>>(
            qkh, qkl, vth, vtl, att);
        gemm_f16<2><<<dim3(DMODEL / 128, ROWS / 128), blk256, GEMM_SMEM>>>(
            att, ow, ob, x_, x_, nullptr, nullptr, nullptr, nullptr,
            ROWS, DMODEL, DMODEL);
        ln_half_kernel<<<ROWS, blk256>>>(x_, ln2_w + i * DMODEL, ln2_b + i * DMODEL, xn);
        gemm_f16<1><<<dim3(FFDIM / 128, ROWS / 128), blk256, GEMM_SMEM>>>(
            xn, f1p, b1, nullptr, nullptr, hbuf, nullptr, nullptr, nullptr,
            ROWS, FFDIM, DMODEL);
        gemm_f16<2><<<dim3(DMODEL / 128, ROWS / 128), blk256, GEMM_SMEM>>>(
            hbuf, f2p, b2, x_, x_, nullptr, nullptr, nullptr, nullptr,
            ROWS, DMODEL, FFDIM);
    }
    ln_kernel<<<ROWS, blk256>>>(x_, final_w, final_b, (float*)d_out);
}